// round 8
// baseline (speedup 1.0000x reference)
#include <cuda_runtime.h>
#include <math.h>
#include <stdint.h>

#define NB 16
#define NA 25200
#define NC 80
#define KPRE 256
#define MAXB 100
#define CAPB 2048
#define SORTF 256
#define SCORE_THR 0.25f
#define IOU_THR 0.1f
#define T0 0.58f

#define DECBLK 99   // ceil(25200/256) blocks per image

// anchors: p5 (20x20) [0,1200), p4 (40x40) [1200,6000), p3 (80x80) [6000,25200)

__device__ float4 g_boxes[NB * NA];
__device__ unsigned long long g_bucket[(size_t)NB * NC * CAPB];
__device__ unsigned int g_bcount[NB * NC];
__device__ float g_fbrow[(size_t)NB * NC * NA];   // fallback scratch only
__device__ unsigned long long g_keys[NB * NC * KPRE];

__constant__ float c_anch[9][2] = {
    {116.f, 90.f}, {156.f, 198.f}, {373.f, 326.f},
    {30.f, 61.f},  {62.f, 45.f},   {59.f, 119.f},
    {10.f, 13.f},  {16.f, 30.f},   {33.f, 23.f}
};

// ---------------------------------------------------------------------------
__global__ void init_kernel()
{
    int i = blockIdx.x * blockDim.x + threadIdx.x;
    if (i < NB * NC) g_bcount[i] = 0;
}

// ---------------------------------------------------------------------------
__device__ __forceinline__ const float* anchor_ptr(
    const float* p5, const float* p4, const float* p3,
    int b, int gi, int& layer, int& g, float& ratio, int& xi, int& yi, int& sub)
{
    const float* fm;
    int base;
    if (gi < 1200)      { layer = 0; base = 0;    g = 20; fm = p5; ratio = 32.f; }
    else if (gi < 6000) { layer = 1; base = 1200; g = 40; fm = p4; ratio = 16.f; }
    else                { layer = 2; base = 6000; g = 80; fm = p3; ratio = 8.f;  }
    int li = gi - base;
    int cell = li / 3;
    sub = li - cell * 3;
    xi = cell % g;
    yi = cell / g;
    return fm + ((size_t)(b * g + yi) * g + xi) * 255 + sub * 85;
}

// ---------------------------------------------------------------------------
// Pass 1: decode boxes + scatter keys with score >= T0 into per-(b,c) buckets
// (identical to passing R7 version)
// ---------------------------------------------------------------------------
__global__ __launch_bounds__(256) void decode_kernel(
    const float* __restrict__ p5, const float* __restrict__ p4, const float* __restrict__ p3)
{
    int tid = threadIdx.x;
    int b = blockIdx.x / DECBLK;
    int blk = blockIdx.x - b * DECBLK;
    int gi = blk * 256 + tid;
    if (gi >= NA) return;

    int layer, g, xi, yi, sub;
    float ratio;
    const float* v = anchor_ptr(p5, p4, p3, b, gi, layer, g, ratio, xi, yi, sub);

    float t0 = v[0], t1 = v[1], t2 = v[2], t3 = v[3], t4 = v[4];
    float sx = 1.f / (1.f + expf(-t0));
    float sy = 1.f / (1.f + expf(-t1));
    float cx = (sx + (float)xi) * ratio;
    float cy = (sy + (float)yi) * ratio;
    float w = expf(t2) * c_anch[layer * 3 + sub][0];
    float h = expf(t3) * c_anch[layer * 3 + sub][1];
    float conf = 1.f / (1.f + expf(-t4));

    g_boxes[b * NA + gi] = make_float4(cx - w * 0.5f, cy - h * 0.5f, cx + w * 0.5f, cy + h * 0.5f);

    float thr = __int_as_float(0x7F800000);
    if (conf > T0) {
        float q = T0 / conf;
        thr = logf(q / (1.f - q)) - 1e-3f;
    }

#pragma unroll
    for (int c = 0; c < NC; c++) {
        float xc = v[5 + c];
        if (xc > thr) {
            float sc = conf * (1.f / (1.f + expf(-xc)));
            if (sc >= T0) {
                int bkt = b * NC + c;
                unsigned pos = atomicAdd(&g_bcount[bkt], 1u);
                if (pos < CAPB)
                    g_bucket[(size_t)bkt * CAPB + pos] =
                        ((unsigned long long)__float_as_uint(sc) << 32)
                        | (unsigned)(0xFFFFFFFFu - (unsigned)gi);
            }
        }
    }
}

// ---------------------------------------------------------------------------
// Pass 2: prune (hist pivot) -> small bitonic sort -> single-warp NMS scan
// ---------------------------------------------------------------------------
__global__ __launch_bounds__(256) void nms_kernel(
    const float* __restrict__ p5, const float* __restrict__ p4, const float* __restrict__ p3)
{
    __shared__ unsigned long long buf[CAPB];     // 16 KB
    __shared__ unsigned int hist[1024];          // 4 KB
    __shared__ int sscan[256];
    __shared__ unsigned int cnt;
    __shared__ int pivot;
    __shared__ int soff;                         // sort base offset in buf
    __shared__ int ssn;                          // sort size
    __shared__ float bx1[KPRE], by1[KPRE], bx2[KPRE], by2[KPRE], barea[KPRE];
    __shared__ unsigned int valw[8], remw_s[8];

    int bc = blockIdx.x;
    int b = bc / NC;
    int c = bc - b * NC;
    int tid = threadIdx.x;

    unsigned n_raw = g_bcount[bc];

    if (n_raw >= KPRE && n_raw <= CAPB) {
        // ---- fast path ----
        const unsigned long long* BK = g_bucket + (size_t)bc * CAPB;
        const float BSCALE = 1023.0f / (1.0f - T0);
        int n = (int)n_raw;

        for (int i = tid; i < 1024; i += 256) hist[i] = 0;
        if (tid == 0) { cnt = 0; pivot = 0; }
        __syncthreads();

        // load keys to smem + histogram scores
        for (int i = tid; i < n; i += 256) {
            unsigned long long k = BK[i];
            buf[i] = k;
            float s = __uint_as_float((unsigned)(k >> 32));
            int bin = (int)((s - T0) * BSCALE);
            bin = bin < 0 ? 0 : (bin > 1023 ? 1023 : bin);
            atomicAdd(&hist[bin], 1u);
        }
        __syncthreads();

        // exact pivot for rank KPRE: thread tid covers descending ranks [4t,4t+4)
        int lc[4];
        int local = 0;
#pragma unroll
        for (int k = 0; k < 4; k++) { lc[k] = (int)hist[1023 - (tid * 4 + k)]; local += lc[k]; }
        sscan[tid] = local;
        __syncthreads();
        for (int off = 1; off < 256; off <<= 1) {
            int vv = sscan[tid];
            int u = (tid >= off) ? sscan[tid - off] : 0;
            __syncthreads();
            sscan[tid] = vv + u;
            __syncthreads();
        }
        int incl = sscan[tid];
        int excl = incl - local;
        if (excl < KPRE && incl >= KPRE) {
            int run = excl;
#pragma unroll
            for (int k = 0; k < 4; k++) {
                run += lc[k];
                if (run >= KPRE) { pivot = 1023 - (tid * 4 + k); break; }
            }
        }
        __syncthreads();
        int P = pivot;

        if (n <= 1024) {
            // compact keys with bin >= P into buf[1024..]
            for (int i = tid; i < n; i += 256) {
                unsigned long long k = buf[i];
                float s = __uint_as_float((unsigned)(k >> 32));
                int bin = (int)((s - T0) * BSCALE);
                bin = bin < 0 ? 0 : (bin > 1023 ? 1023 : bin);
                if (bin >= P) {
                    unsigned pos = atomicAdd(&cnt, 1u);
                    buf[1024 + pos] = k;
                }
            }
            __syncthreads();
            int m = (int)cnt;
            int sp = SORTF;
            while (sp < m) sp <<= 1;   // 256/512/1024
            if (tid == 0) { soff = 1024; ssn = sp; }
            for (int i = tid; i < sp; i += 256)
                if (i >= m) buf[1024 + i] = 0ULL;
            __syncthreads();
        } else {
            if (tid == 0) { soff = 0; ssn = CAPB; }
            for (int i = tid; i < CAPB; i += 256)
                if (i >= n) buf[i] = 0ULL;
            __syncthreads();
        }
    } else {
        // ---- exact fallback: recompute row, hist-pivot over (0.25,1), collect ----
        float* row = g_fbrow + (size_t)bc * NA;
        const float FSCALE = 1023.0f / 0.75f;
        for (int i = tid; i < 1024; i += 256) hist[i] = 0;
        if (tid == 0) { cnt = 0; pivot = 0; }
        __syncthreads();

        for (int gi = tid; gi < NA; gi += 256) {
            int layer, g, xi, yi, sub;
            float ratio;
            const float* v = anchor_ptr(p5, p4, p3, b, gi, layer, g, ratio, xi, yi, sub);
            float conf = 1.f / (1.f + expf(-v[4]));
            float sc = conf * (1.f / (1.f + expf(-v[5 + c])));
            float s = (sc > SCORE_THR) ? sc : -1.f;
            row[gi] = s;
            if (s > 0.f) {
                int bin = (int)((s - SCORE_THR) * FSCALE);
                bin = bin < 0 ? 0 : (bin > 1023 ? 1023 : bin);
                atomicAdd(&hist[bin], 1u);
            }
        }
        __syncthreads();

        int lc[4];
        int local = 0;
#pragma unroll
        for (int k = 0; k < 4; k++) { lc[k] = (int)hist[1023 - (tid * 4 + k)]; local += lc[k]; }
        sscan[tid] = local;
        __syncthreads();
        for (int off = 1; off < 256; off <<= 1) {
            int vv = sscan[tid];
            int u = (tid >= off) ? sscan[tid - off] : 0;
            __syncthreads();
            sscan[tid] = vv + u;
            __syncthreads();
        }
        int incl = sscan[tid];
        int excl = incl - local;
        if (excl < KPRE && incl >= KPRE) {
            int run = excl;
#pragma unroll
            for (int k = 0; k < 4; k++) {
                run += lc[k];
                if (run >= KPRE) { pivot = 1023 - (tid * 4 + k); break; }
            }
        }
        __syncthreads();
        int P = pivot;

        for (int gi = tid; gi < NA; gi += 256) {
            float s = row[gi];
            if (s > 0.f) {
                int bin = (int)((s - SCORE_THR) * FSCALE);
                bin = bin < 0 ? 0 : (bin > 1023 ? 1023 : bin);
                if (bin >= P) {
                    unsigned pos = atomicAdd(&cnt, 1u);
                    if (pos < 1024)
                        buf[pos] = ((unsigned long long)__float_as_uint(s) << 32)
                                 | (unsigned)(0xFFFFFFFFu - (unsigned)gi);
                }
            }
        }
        __syncthreads();
        int m = cnt < 1024u ? (int)cnt : 1024;
        if (tid == 0) { soff = 0; ssn = 1024; }
        for (int i = tid; i < 1024; i += 256)
            if (i >= m) buf[i] = 0ULL;
        __syncthreads();
    }

    unsigned long long* sb = buf + soff;
    int sn = ssn;

    // bitonic sort descending
    for (int k = 2; k <= sn; k <<= 1) {
        for (int j = k >> 1; j > 0; j >>= 1) {
            for (int i = tid; i < sn; i += 256) {
                int ixj = i ^ j;
                if (ixj > i) {
                    unsigned long long A = sb[i], Bv = sb[ixj];
                    bool desc = ((i & k) == 0);
                    if (desc ? (A < Bv) : (A > Bv)) { sb[i] = Bv; sb[ixj] = A; }
                }
            }
            __syncthreads();
        }
    }

    // top-256 -> per-thread + smem box arrays
    unsigned long long key = sb[tid];
    bool valid = key != 0ULL;
    float sc = -1.f;
    int a = 0;
    if (valid) {
        sc = __uint_as_float((unsigned)(key >> 32));
        a = (int)(0xFFFFFFFFu - (unsigned)(key & 0xFFFFFFFFu));
    }
    float4 bb = valid ? g_boxes[b * NA + a] : make_float4(0.f, 0.f, 0.f, 0.f);
    float area = fmaxf(bb.z - bb.x, 0.f) * fmaxf(bb.w - bb.y, 0.f);
    bx1[tid] = bb.x; by1[tid] = bb.y; bx2[tid] = bb.z; by2[tid] = bb.w;
    barea[tid] = area;

    unsigned vb = __ballot_sync(0xFFFFFFFFu, valid);
    if ((tid & 31) == 0) { valw[tid >> 5] = vb; remw_s[tid >> 5] = ~vb; }
    __syncthreads();

    // single-warp greedy NMS scan: removed mask in 8 lane registers, IoU on the fly
    if (tid < 32) {
        unsigned rem = (tid < 8) ? remw_s[tid] : 0u;
        for (int i = 0; i < KPRE; i++) {
            unsigned rw = __shfl_sync(0xFFFFFFFFu, rem, i >> 5);
            if (!((rw >> (i & 31)) & 1u)) {
                float x1i = bx1[i], y1i = by1[i], x2i = bx2[i], y2i = by2[i], ai = barea[i];
#pragma unroll
                for (int m2 = 0; m2 < 8; m2++) {
                    int j = m2 * 32 + tid;
                    float iw = fminf(x2i, bx2[j]) - fmaxf(x1i, bx1[j]);
                    float ih = fminf(y2i, by2[j]) - fmaxf(y1i, by1[j]);
                    iw = fmaxf(iw, 0.f);
                    ih = fmaxf(ih, 0.f);
                    float inter = iw * ih;
                    float uni = ai + barea[j] - inter;
                    float iou = inter / fmaxf(uni, 1e-9f);
                    unsigned bal = __ballot_sync(0xFFFFFFFFu, iou > IOU_THR && j > i);
                    if (tid == m2) rem |= bal;
                }
            }
        }
        if (tid < 8) remw_s[tid] = rem;
    }
    __syncthreads();

    // keep = valid & !removed, capped at MAXB by inclusive rank (R5-proven logic)
    int w = tid >> 5, bpos = tid & 31;
    unsigned kw = valw[w] & ~remw_s[w];
    bool keep = (kw >> bpos) & 1u;
    if (keep) {
        int rank = __popc(kw & (0xFFFFFFFFu >> (31 - bpos)));
        for (int ww = 0; ww < w; ww++) rank += __popc(valw[ww] & ~remw_s[ww]);
        keep = rank <= MAXB;
    }

    unsigned long long outkey = 0ULL;
    if (keep) {
        int flatpos = c * KPRE + tid;
        unsigned low = ((unsigned)(20479 - flatpos) << 15) | (unsigned)a;
        outkey = ((unsigned long long)__float_as_uint(sc) << 32) | low;
    }
    g_keys[(size_t)b * NC * KPRE + c * KPRE + tid] = outkey;
}

// ---------------------------------------------------------------------------
// Pass 3: per-image top-100 (proven form, 1024-bin hist)
// ---------------------------------------------------------------------------
__global__ __launch_bounds__(256) void final_kernel(float* __restrict__ out)
{
    __shared__ unsigned int hist[1024];
    __shared__ unsigned long long buf[SORTF];
    __shared__ int sscan[256];
    __shared__ unsigned int cnt;
    __shared__ int pivot;

    int b = blockIdx.x;
    int tid = threadIdx.x;
    const unsigned long long* K = g_keys + (size_t)b * NC * KPRE;
    const float FSCALE = 1023.0f / 0.75f;

    for (int i = tid; i < 1024; i += 256) hist[i] = 0;
    if (tid == 0) { cnt = 0; pivot = 0; }
    __syncthreads();

    for (int i = tid; i < NC * KPRE; i += 256) {
        unsigned long long k = K[i];
        if (k) {
            float s = __uint_as_float((unsigned)(k >> 32));
            int bin = (int)((s - SCORE_THR) * FSCALE);
            bin = bin < 0 ? 0 : (bin > 1023 ? 1023 : bin);
            atomicAdd(&hist[bin], 1u);
        }
    }
    __syncthreads();

    int lc[4];
    int local = 0;
#pragma unroll
    for (int kk = 0; kk < 4; kk++) { lc[kk] = (int)hist[1023 - (tid * 4 + kk)]; local += lc[kk]; }
    sscan[tid] = local;
    __syncthreads();
    for (int off = 1; off < 256; off <<= 1) {
        int vv = sscan[tid];
        int u = (tid >= off) ? sscan[tid - off] : 0;
        __syncthreads();
        sscan[tid] = vv + u;
        __syncthreads();
    }
    int incl = sscan[tid];
    int excl = incl - local;
    if (excl < MAXB && incl >= MAXB) {
        int run = excl;
#pragma unroll
        for (int kk = 0; kk < 4; kk++) {
            run += lc[kk];
            if (run >= MAXB) { pivot = 1023 - (tid * 4 + kk); break; }
        }
    }
    __syncthreads();
    int P = pivot;

    for (int i = tid; i < NC * KPRE; i += 256) {
        unsigned long long k = K[i];
        if (k) {
            float s = __uint_as_float((unsigned)(k >> 32));
            int bin = (int)((s - SCORE_THR) * FSCALE);
            bin = bin < 0 ? 0 : (bin > 1023 ? 1023 : bin);
            if (bin >= P) {
                unsigned pos = atomicAdd(&cnt, 1u);
                if (pos < SORTF) buf[pos] = k;
            }
        }
    }
    __syncthreads();
    int m = cnt < SORTF ? (int)cnt : SORTF;
    for (int i = tid; i < SORTF; i += 256)
        if (i >= m) buf[i] = 0ULL;
    __syncthreads();

    for (int k2 = 2; k2 <= SORTF; k2 <<= 1) {
        for (int j = k2 >> 1; j > 0; j >>= 1) {
            int ixj = tid ^ j;
            if (ixj > tid) {
                unsigned long long A = buf[tid], Bv = buf[ixj];
                bool desc = ((tid & k2) == 0);
                if (desc ? (A < Bv) : (A > Bv)) { buf[tid] = Bv; buf[ixj] = A; }
            }
            __syncthreads();
        }
    }

    if (tid < MAXB) {
        unsigned long long k = buf[tid];
        float x1 = -1.f, y1 = -1.f, x2 = -1.f, y2 = -1.f, scv = -1.f, lab = -1.f;
        if (k) {
            unsigned bits = (unsigned)(k >> 32);
            scv = __uint_as_float(bits);
            unsigned low = (unsigned)(k & 0xFFFFFFFFu);
            int flatpos = 20479 - (int)(low >> 15);
            int a = (int)(low & 0x7FFFu);
            int cls = flatpos >> 8;
            float4 bb = g_boxes[b * NA + a];
            x1 = bb.x; y1 = bb.y; x2 = bb.z; y2 = bb.w;
            lab = (float)cls;
        }
        float* ob = out;
        float* os = out + NB * MAXB * 4;
        float* ol = out + NB * MAXB * 5;
        ob[(b * MAXB + tid) * 4 + 0] = x1;
        ob[(b * MAXB + tid) * 4 + 1] = y1;
        ob[(b * MAXB + tid) * 4 + 2] = x2;
        ob[(b * MAXB + tid) * 4 + 3] = y2;
        os[b * MAXB + tid] = scv;
        ol[b * MAXB + tid] = lab;
    }
}

// ---------------------------------------------------------------------------
extern "C" void kernel_launch(void* const* d_in, const int* in_sizes, int n_in,
                              void* d_out, int out_size)
{
    const float* p5 = (const float*)d_in[0];
    const float* p4 = (const float*)d_in[1];
    const float* p3 = (const float*)d_in[2];
    float* out = (float*)d_out;

    init_kernel<<<(NB * NC + 255) / 256, 256>>>();
    decode_kernel<<<NB * DECBLK, 256>>>(p5, p4, p3);
    nms_kernel<<<NB * NC, 256>>>(p5, p4, p3);
    final_kernel<<<NB, 256>>>(out);
}

// round 9
// speedup vs baseline: 1.8303x; 1.8303x over previous
#include <cuda_runtime.h>
#include <math.h>
#include <stdint.h>

#define NB 16
#define NA 25200
#define NC 80
#define KPRE 256
#define MAXB 100
#define CAPB 2048
#define SORTF 256
#define SCORE_THR 0.25f
#define IOU_THR 0.1f
#define T0 0.58f

#define CELLS 40
#define ANCH (CELLS * 3)          // 120 anchors per decode block
#define STG (CELLS * 255)         // 10200 floats staged

// anchors: p5 (20x20) [0,1200), p4 (40x40) [1200,6000), p3 (80x80) [6000,25200)

__device__ float4 g_boxes[NB * NA];
__device__ unsigned long long g_bucket[(size_t)NB * NC * CAPB];
__device__ unsigned int g_bcount[NB * NC];
__device__ float g_fbrow[(size_t)NB * NC * NA];   // fallback scratch only
__device__ unsigned long long g_keys[NB * NC * KPRE];

__constant__ float c_anch[9][2] = {
    {116.f, 90.f}, {156.f, 198.f}, {373.f, 326.f},
    {30.f, 61.f},  {62.f, 45.f},   {59.f, 119.f},
    {10.f, 13.f},  {16.f, 30.f},   {33.f, 23.f}
};

// ---------------------------------------------------------------------------
__global__ void init_kernel()
{
    int i = blockIdx.x * blockDim.x + threadIdx.x;
    if (i < NB * NC) g_bcount[i] = 0;
}

// ---------------------------------------------------------------------------
__device__ __forceinline__ const float* anchor_ptr(
    const float* p5, const float* p4, const float* p3,
    int b, int gi, int& layer, int& g, float& ratio, int& xi, int& yi, int& sub)
{
    const float* fm;
    int base;
    if (gi < 1200)      { layer = 0; base = 0;    g = 20; fm = p5; ratio = 32.f; }
    else if (gi < 6000) { layer = 1; base = 1200; g = 40; fm = p4; ratio = 16.f; }
    else                { layer = 2; base = 6000; g = 80; fm = p3; ratio = 8.f;  }
    int li = gi - base;
    int cell = li / 3;
    sub = li - cell * 3;
    xi = cell % g;
    yi = cell / g;
    return fm + ((size_t)(b * g + yi) * g + xi) * 255 + sub * 85;
}

// ---------------------------------------------------------------------------
// Pass 1: STAGED decode + T0 bucket scatter.
// Block = 40 cells (120 anchors) of one (image, layer), 256 threads.
// ---------------------------------------------------------------------------
__global__ __launch_bounds__(256) void decode_kernel(
    const float* __restrict__ p5, const float* __restrict__ p4, const float* __restrict__ p3)
{
    __shared__ float s[STG];          // 40800 B
    __shared__ float sthr[ANCH];
    __shared__ float sconf[ANCH];

    int blk = blockIdx.x;
    int b = blk / 210;
    int r = blk - b * 210;

    const float* fm;
    int g, layerbase, cellbase, arow;
    float ratio;
    if (r < 10)      { fm = p5; g = 20; layerbase = 0;    cellbase = r * CELLS;        arow = 0; ratio = 32.f; }
    else if (r < 50) { fm = p4; g = 40; layerbase = 1200; cellbase = (r - 10) * CELLS; arow = 3; ratio = 16.f; }
    else             { fm = p3; g = 80; layerbase = 6000; cellbase = (r - 50) * CELLS; arow = 6; ratio = 8.f;  }

    int tid = threadIdx.x;

    // stage 40 cells coalesced
    const float* src = fm + ((size_t)b * g * g + cellbase) * 255;
    for (int i = tid; i < STG; i += 256) s[i] = src[i];
    __syncthreads();

    // phase 1: decode boxes + thresholds for 120 anchors
    if (tid < ANCH) {
        int a = tid;
        const float* v = s + a * 85;   // stride 85 words: conflict-free
        int cellg = cellbase + a / 3;
        int sub = a % 3;
        int xi = cellg % g;
        int yi = cellg / g;

        float t0 = v[0], t1 = v[1], t2 = v[2], t3 = v[3], t4 = v[4];
        float sx = 1.f / (1.f + expf(-t0));
        float sy = 1.f / (1.f + expf(-t1));
        float cx = (sx + (float)xi) * ratio;
        float cy = (sy + (float)yi) * ratio;
        float w = expf(t2) * c_anch[arow + sub][0];
        float h = expf(t3) * c_anch[arow + sub][1];
        float conf = 1.f / (1.f + expf(-t4));

        int gi = layerbase + cellg * 3 + sub;
        g_boxes[b * NA + gi] = make_float4(cx - w * 0.5f, cy - h * 0.5f, cx + w * 0.5f, cy + h * 0.5f);

        float thr = __int_as_float(0x7F800000);
        if (conf > T0) {
            float q = T0 / conf;
            thr = logf(q / (1.f - q)) - 1e-3f;
        }
        sthr[a] = thr;
        sconf[a] = conf;
    }
    __syncthreads();

    // phase 2: 120 anchors x 80 classes, scatter passing keys to buckets
    int abase = layerbase + cellbase * 3;
    for (int idx = tid; idx < ANCH * NC; idx += 256) {
        int c = idx / ANCH;
        int a = idx - c * ANCH;
        float xc = s[a * 85 + 5 + c];
        if (xc > sthr[a]) {
            float sc = sconf[a] * (1.f / (1.f + expf(-xc)));   // identical math to R7
            if (sc >= T0) {
                int gi = abase + a;
                int bkt = b * NC + c;
                unsigned pos = atomicAdd(&g_bcount[bkt], 1u);
                if (pos < CAPB)
                    g_bucket[(size_t)bkt * CAPB + pos] =
                        ((unsigned long long)__float_as_uint(sc) << 32)
                        | (unsigned)(0xFFFFFFFFu - (unsigned)gi);
            }
        }
    }
}

// ---------------------------------------------------------------------------
// Pass 2: prune (hist pivot -> compact) -> small bitonic sort -> barrier NMS
// ---------------------------------------------------------------------------
__global__ __launch_bounds__(256) void nms_kernel(
    const float* __restrict__ p5, const float* __restrict__ p4, const float* __restrict__ p3)
{
    __shared__ unsigned long long buf[CAPB];   // 16 KB
    __shared__ unsigned int hist[1024];        // 4 KB
    __shared__ int sscan[256];
    __shared__ unsigned int cnt;
    __shared__ int pivot;
    __shared__ int soff, ssn;
    __shared__ float4 bbox[KPRE];              // 4 KB
    __shared__ float barea_s[KPRE];
    __shared__ int supp[KPRE];

    int bc = blockIdx.x;
    int b = bc / NC;
    int c = bc - b * NC;
    int tid = threadIdx.x;

    unsigned n_raw = g_bcount[bc];

    if (n_raw >= KPRE && n_raw <= CAPB) {
        // ---- fast path ----
        const unsigned long long* BK = g_bucket + (size_t)bc * CAPB;
        const float BSCALE = 1023.0f / (1.0f - T0);
        int n = (int)n_raw;

        for (int i = tid; i < 1024; i += 256) hist[i] = 0;
        if (tid == 0) { cnt = 0; pivot = 0; }
        __syncthreads();

        for (int i = tid; i < n; i += 256) {
            unsigned long long k = BK[i];
            buf[i] = k;
            float s = __uint_as_float((unsigned)(k >> 32));
            int bin = (int)((s - T0) * BSCALE);
            bin = bin < 0 ? 0 : (bin > 1023 ? 1023 : bin);
            atomicAdd(&hist[bin], 1u);
        }
        __syncthreads();

        // exact pivot for rank KPRE: thread tid covers descending ranks [4t,4t+4)
        int lc[4];
        int local = 0;
#pragma unroll
        for (int k = 0; k < 4; k++) { lc[k] = (int)hist[1023 - (tid * 4 + k)]; local += lc[k]; }
        sscan[tid] = local;
        __syncthreads();
        for (int off = 1; off < 256; off <<= 1) {
            int vv = sscan[tid];
            int u = (tid >= off) ? sscan[tid - off] : 0;
            __syncthreads();
            sscan[tid] = vv + u;
            __syncthreads();
        }
        int incl = sscan[tid];
        int excl = incl - local;
        if (excl < KPRE && incl >= KPRE) {
            int run = excl;
#pragma unroll
            for (int k = 0; k < 4; k++) {
                run += lc[k];
                if (run >= KPRE) { pivot = 1023 - (tid * 4 + k); break; }
            }
        }
        __syncthreads();
        int P = pivot;

        if (n <= 1024) {
            // compact keys with bin >= P into buf[1024..1024+m)
            for (int i = tid; i < n; i += 256) {
                unsigned long long k = buf[i];
                float s = __uint_as_float((unsigned)(k >> 32));
                int bin = (int)((s - T0) * BSCALE);
                bin = bin < 0 ? 0 : (bin > 1023 ? 1023 : bin);
                if (bin >= P) {
                    unsigned pos = atomicAdd(&cnt, 1u);
                    buf[1024 + pos] = k;
                }
            }
            __syncthreads();
            int m = (int)cnt;
            int sp = SORTF;
            while (sp < m) sp <<= 1;       // 256/512/1024 (m <= n <= 1024)
            if (tid == 0) { soff = 1024; ssn = sp; }
            for (int i = tid; i < sp; i += 256)
                if (i >= m) buf[1024 + i] = 0ULL;
            __syncthreads();
        } else {
            if (tid == 0) { soff = 0; ssn = CAPB; }
            for (int i = tid; i < CAPB; i += 256)
                if (i >= n) buf[i] = 0ULL;
            __syncthreads();
        }
    } else {
        // ---- exact fallback: recompute row, hist-pivot over (0.25,1), collect ----
        float* row = g_fbrow + (size_t)bc * NA;
        const float FSCALE = 1023.0f / 0.75f;
        for (int i = tid; i < 1024; i += 256) hist[i] = 0;
        if (tid == 0) { cnt = 0; pivot = 0; }
        __syncthreads();

        for (int gi = tid; gi < NA; gi += 256) {
            int layer, g, xi, yi, sub;
            float ratio;
            const float* v = anchor_ptr(p5, p4, p3, b, gi, layer, g, ratio, xi, yi, sub);
            float conf = 1.f / (1.f + expf(-v[4]));
            float sc = conf * (1.f / (1.f + expf(-v[5 + c])));
            float s = (sc > SCORE_THR) ? sc : -1.f;
            row[gi] = s;
            if (s > 0.f) {
                int bin = (int)((s - SCORE_THR) * FSCALE);
                bin = bin < 0 ? 0 : (bin > 1023 ? 1023 : bin);
                atomicAdd(&hist[bin], 1u);
            }
        }
        __syncthreads();

        int lc[4];
        int local = 0;
#pragma unroll
        for (int k = 0; k < 4; k++) { lc[k] = (int)hist[1023 - (tid * 4 + k)]; local += lc[k]; }
        sscan[tid] = local;
        __syncthreads();
        for (int off = 1; off < 256; off <<= 1) {
            int vv = sscan[tid];
            int u = (tid >= off) ? sscan[tid - off] : 0;
            __syncthreads();
            sscan[tid] = vv + u;
            __syncthreads();
        }
        int incl = sscan[tid];
        int excl = incl - local;
        if (excl < KPRE && incl >= KPRE) {
            int run = excl;
#pragma unroll
            for (int k = 0; k < 4; k++) {
                run += lc[k];
                if (run >= KPRE) { pivot = 1023 - (tid * 4 + k); break; }
            }
        }
        __syncthreads();
        int P = pivot;

        for (int gi = tid; gi < NA; gi += 256) {
            float s = row[gi];
            if (s > 0.f) {
                int bin = (int)((s - SCORE_THR) * FSCALE);
                bin = bin < 0 ? 0 : (bin > 1023 ? 1023 : bin);
                if (bin >= P) {
                    unsigned pos = atomicAdd(&cnt, 1u);
                    if (pos < 1024)
                        buf[pos] = ((unsigned long long)__float_as_uint(s) << 32)
                                 | (unsigned)(0xFFFFFFFFu - (unsigned)gi);
                }
            }
        }
        __syncthreads();
        int m = cnt < 1024u ? (int)cnt : 1024;
        if (tid == 0) { soff = 0; ssn = 1024; }
        for (int i = tid; i < 1024; i += 256)
            if (i >= m) buf[i] = 0ULL;
        __syncthreads();
    }

    unsigned long long* sb = buf + soff;
    int sn = ssn;

    // bitonic sort descending
    for (int k = 2; k <= sn; k <<= 1) {
        for (int j = k >> 1; j > 0; j >>= 1) {
            for (int i = tid; i < sn; i += 256) {
                int ixj = i ^ j;
                if (ixj > i) {
                    unsigned long long A = sb[i], Bv = sb[ixj];
                    bool desc = ((i & k) == 0);
                    if (desc ? (A < Bv) : (A > Bv)) { sb[i] = Bv; sb[ixj] = A; }
                }
            }
            __syncthreads();
        }
    }

    // top-256 -> smem box arrays (score/anchor stay in registers)
    unsigned long long key = sb[tid];
    bool valid = key != 0ULL;
    float sc = -1.f;
    int a = 0;
    if (valid) {
        sc = __uint_as_float((unsigned)(key >> 32));
        a = (int)(0xFFFFFFFFu - (unsigned)(key & 0xFFFFFFFFu));
    }
    float4 bb = valid ? g_boxes[b * NA + a] : make_float4(0.f, 0.f, 0.f, 0.f);
    float area = fmaxf(bb.z - bb.x, 0.f) * fmaxf(bb.w - bb.y, 0.f);
    bbox[tid] = bb;
    barea_s[tid] = area;
    supp[tid] = valid ? 0 : 1;
    __syncthreads();

    // greedy NMS barrier loop (proven R7 form, exact ref IoU formula)
    bool msupp = !valid;
    for (int i = 0; i < KPRE - 1; i++) {
        if (!supp[i] && tid > i && !msupp) {
            float4 ob = bbox[i];
            float iw = fminf(bb.z, ob.z) - fmaxf(bb.x, ob.x);
            float ih = fminf(bb.w, ob.w) - fmaxf(bb.y, ob.y);
            iw = fmaxf(iw, 0.f);
            ih = fmaxf(ih, 0.f);
            float inter = iw * ih;
            float uni = area + barea_s[i] - inter;
            float iou = inter / fmaxf(uni, 1e-9f);
            if (iou > IOU_THR) { msupp = true; supp[tid] = 1; }
        }
        __syncthreads();
    }

    // keep + cumsum cap at MAXB
    int keep = msupp ? 0 : 1;
    sscan[tid] = keep;
    __syncthreads();
    for (int off = 1; off < 256; off <<= 1) {
        int vv = sscan[tid];
        int u = (tid >= off) ? sscan[tid - off] : 0;
        __syncthreads();
        sscan[tid] = vv + u;
        __syncthreads();
    }
    int rank = sscan[tid];
    keep = keep && (rank <= MAXB);

    unsigned long long outkey = 0ULL;
    if (keep) {
        int flatpos = c * KPRE + tid;
        unsigned low = ((unsigned)(20479 - flatpos) << 15) | (unsigned)a;
        outkey = ((unsigned long long)__float_as_uint(sc) << 32) | low;
    }
    g_keys[(size_t)b * NC * KPRE + c * KPRE + tid] = outkey;
}

// ---------------------------------------------------------------------------
// Pass 3: per-image top-100 (proven form)
// ---------------------------------------------------------------------------
__global__ __launch_bounds__(256) void final_kernel(float* __restrict__ out)
{
    __shared__ unsigned int hist[1024];
    __shared__ unsigned long long buf[SORTF];
    __shared__ int sscan[256];
    __shared__ unsigned int cnt;
    __shared__ int pivot;

    int b = blockIdx.x;
    int tid = threadIdx.x;
    const unsigned long long* K = g_keys + (size_t)b * NC * KPRE;
    const float FSCALE = 1023.0f / 0.75f;

    for (int i = tid; i < 1024; i += 256) hist[i] = 0;
    if (tid == 0) { cnt = 0; pivot = 0; }
    __syncthreads();

    for (int i = tid; i < NC * KPRE; i += 256) {
        unsigned long long k = K[i];
        if (k) {
            float s = __uint_as_float((unsigned)(k >> 32));
            int bin = (int)((s - SCORE_THR) * FSCALE);
            bin = bin < 0 ? 0 : (bin > 1023 ? 1023 : bin);
            atomicAdd(&hist[bin], 1u);
        }
    }
    __syncthreads();

    int lc[4];
    int local = 0;
#pragma unroll
    for (int kk = 0; kk < 4; kk++) { lc[kk] = (int)hist[1023 - (tid * 4 + kk)]; local += lc[kk]; }
    sscan[tid] = local;
    __syncthreads();
    for (int off = 1; off < 256; off <<= 1) {
        int vv = sscan[tid];
        int u = (tid >= off) ? sscan[tid - off] : 0;
        __syncthreads();
        sscan[tid] = vv + u;
        __syncthreads();
    }
    int incl = sscan[tid];
    int excl = incl - local;
    if (excl < MAXB && incl >= MAXB) {
        int run = excl;
#pragma unroll
        for (int kk = 0; kk < 4; kk++) {
            run += lc[kk];
            if (run >= MAXB) { pivot = 1023 - (tid * 4 + kk); break; }
        }
    }
    __syncthreads();
    int P = pivot;

    for (int i = tid; i < NC * KPRE; i += 256) {
        unsigned long long k = K[i];
        if (k) {
            float s = __uint_as_float((unsigned)(k >> 32));
            int bin = (int)((s - SCORE_THR) * FSCALE);
            bin = bin < 0 ? 0 : (bin > 1023 ? 1023 : bin);
            if (bin >= P) {
                unsigned pos = atomicAdd(&cnt, 1u);
                if (pos < SORTF) buf[pos] = k;
            }
        }
    }
    __syncthreads();
    int m = cnt < SORTF ? (int)cnt : SORTF;
    for (int i = tid; i < SORTF; i += 256)
        if (i >= m) buf[i] = 0ULL;
    __syncthreads();

    for (int k2 = 2; k2 <= SORTF; k2 <<= 1) {
        for (int j = k2 >> 1; j > 0; j >>= 1) {
            int ixj = tid ^ j;
            if (ixj > tid) {
                unsigned long long A = buf[tid], Bv = buf[ixj];
                bool desc = ((tid & k2) == 0);
                if (desc ? (A < Bv) : (A > Bv)) { buf[tid] = Bv; buf[ixj] = A; }
            }
            __syncthreads();
        }
    }

    if (tid < MAXB) {
        unsigned long long k = buf[tid];
        float x1 = -1.f, y1 = -1.f, x2 = -1.f, y2 = -1.f, scv = -1.f, lab = -1.f;
        if (k) {
            unsigned bits = (unsigned)(k >> 32);
            scv = __uint_as_float(bits);
            unsigned low = (unsigned)(k & 0xFFFFFFFFu);
            int flatpos = 20479 - (int)(low >> 15);
            int a = (int)(low & 0x7FFFu);
            int cls = flatpos >> 8;
            float4 bb = g_boxes[b * NA + a];
            x1 = bb.x; y1 = bb.y; x2 = bb.z; y2 = bb.w;
            lab = (float)cls;
        }
        float* ob = out;
        float* os = out + NB * MAXB * 4;
        float* ol = out + NB * MAXB * 5;
        ob[(b * MAXB + tid) * 4 + 0] = x1;
        ob[(b * MAXB + tid) * 4 + 1] = y1;
        ob[(b * MAXB + tid) * 4 + 2] = x2;
        ob[(b * MAXB + tid) * 4 + 3] = y2;
        os[b * MAXB + tid] = scv;
        ol[b * MAXB + tid] = lab;
    }
}

// ---------------------------------------------------------------------------
extern "C" void kernel_launch(void* const* d_in, const int* in_sizes, int n_in,
                              void* d_out, int out_size)
{
    const float* p5 = (const float*)d_in[0];
    const float* p4 = (const float*)d_in[1];
    const float* p3 = (const float*)d_in[2];
    float* out = (float*)d_out;

    init_kernel<<<(NB * NC + 255) / 256, 256>>>();
    decode_kernel<<<NB * 210, 256>>>(p5, p4, p3);
    nms_kernel<<<NB * NC, 256>>>(p5, p4, p3);
    final_kernel<<<NB, 256>>>(out);
}

// round 10
// speedup vs baseline: 2.4213x; 1.3229x over previous
#include <cuda_runtime.h>
#include <math.h>
#include <stdint.h>

#define NB 16
#define NA 25200
#define NC 80
#define KPRE 256
#define MAXB 100
#define CAPB 2048
#define SORTF 256
#define SCORE_THR 0.25f
#define IOU_THR 0.1f
#define T0 0.58f

#define DECBLK 99   // ceil(25200/256) blocks per image

// anchors: p5 (20x20) [0,1200), p4 (40x40) [1200,6000), p3 (80x80) [6000,25200)

__device__ float4 g_boxes[NB * NA];
__device__ unsigned long long g_bucket[(size_t)NB * NC * CAPB];
__device__ unsigned int g_bcount[NB * NC];
__device__ float g_fbrow[(size_t)NB * NC * NA];   // fallback scratch only
__device__ unsigned long long g_keys[NB * NC * KPRE];

__constant__ float c_anch[9][2] = {
    {116.f, 90.f}, {156.f, 198.f}, {373.f, 326.f},
    {30.f, 61.f},  {62.f, 45.f},   {59.f, 119.f},
    {10.f, 13.f},  {16.f, 30.f},   {33.f, 23.f}
};

// ---------------------------------------------------------------------------
__global__ void init_kernel()
{
    int i = blockIdx.x * blockDim.x + threadIdx.x;
    if (i < NB * NC) g_bcount[i] = 0;
}

// ---------------------------------------------------------------------------
__device__ __forceinline__ const float* anchor_ptr(
    const float* p5, const float* p4, const float* p3,
    int b, int gi, int& layer, int& g, float& ratio, int& xi, int& yi, int& sub)
{
    const float* fm;
    int base;
    if (gi < 1200)      { layer = 0; base = 0;    g = 20; fm = p5; ratio = 32.f; }
    else if (gi < 6000) { layer = 1; base = 1200; g = 40; fm = p4; ratio = 16.f; }
    else                { layer = 2; base = 6000; g = 80; fm = p3; ratio = 8.f;  }
    int li = gi - base;
    int cell = li / 3;
    sub = li - cell * 3;
    xi = cell % g;
    yi = cell / g;
    return fm + ((size_t)(b * g + yi) * g + xi) * 255 + sub * 85;
}

// ---------------------------------------------------------------------------
// Pass 1: decode boxes + scatter keys with score >= T0 into per-(b,c) buckets
// (byte-identical to the passing 390us R7 version)
// ---------------------------------------------------------------------------
__global__ __launch_bounds__(256) void decode_kernel(
    const float* __restrict__ p5, const float* __restrict__ p4, const float* __restrict__ p3)
{
    int tid = threadIdx.x;
    int b = blockIdx.x / DECBLK;
    int blk = blockIdx.x - b * DECBLK;
    int gi = blk * 256 + tid;
    if (gi >= NA) return;

    int layer, g, xi, yi, sub;
    float ratio;
    const float* v = anchor_ptr(p5, p4, p3, b, gi, layer, g, ratio, xi, yi, sub);

    float t0 = v[0], t1 = v[1], t2 = v[2], t3 = v[3], t4 = v[4];
    float sx = 1.f / (1.f + expf(-t0));
    float sy = 1.f / (1.f + expf(-t1));
    float cx = (sx + (float)xi) * ratio;
    float cy = (sy + (float)yi) * ratio;
    float w = expf(t2) * c_anch[layer * 3 + sub][0];
    float h = expf(t3) * c_anch[layer * 3 + sub][1];
    float conf = 1.f / (1.f + expf(-t4));

    g_boxes[b * NA + gi] = make_float4(cx - w * 0.5f, cy - h * 0.5f, cx + w * 0.5f, cy + h * 0.5f);

    float thr = __int_as_float(0x7F800000);
    if (conf > T0) {
        float q = T0 / conf;
        thr = logf(q / (1.f - q)) - 1e-3f;
    }

#pragma unroll
    for (int c = 0; c < NC; c++) {
        float xc = v[5 + c];
        if (xc > thr) {
            float sc = conf * (1.f / (1.f + expf(-xc)));
            if (sc >= T0) {
                int bkt = b * NC + c;
                unsigned pos = atomicAdd(&g_bcount[bkt], 1u);
                if (pos < CAPB)
                    g_bucket[(size_t)bkt * CAPB + pos] =
                        ((unsigned long long)__float_as_uint(sc) << 32)
                        | (unsigned)(0xFFFFFFFFu - (unsigned)gi);
            }
        }
    }
}

// ---------------------------------------------------------------------------
// Pass 2: prune (hist pivot -> compact) -> small bitonic sort -> barrier NMS
// (R7 structure; ONLY the sort-prep changed vs R7)
// ---------------------------------------------------------------------------
__global__ __launch_bounds__(256) void nms_kernel(
    const float* __restrict__ p5, const float* __restrict__ p4, const float* __restrict__ p3)
{
    __shared__ unsigned long long buf[CAPB];   // 16 KB
    __shared__ unsigned int hist[1024];        // 4 KB
    __shared__ int sscan[256];
    __shared__ unsigned int cnt;
    __shared__ int pivot;
    __shared__ int soff, ssn;
    __shared__ float bx1[KPRE], by1[KPRE], bx2[KPRE], by2[KPRE], barea[KPRE], bscore[KPRE];
    __shared__ int banch[KPRE];
    __shared__ int supp[KPRE];

    int bc = blockIdx.x;
    int b = bc / NC;
    int c = bc - b * NC;
    int tid = threadIdx.x;

    unsigned n_raw = g_bcount[bc];

    if (n_raw >= KPRE && n_raw <= CAPB) {
        // ---- fast path: load keys + histogram scores ----
        const unsigned long long* BK = g_bucket + (size_t)bc * CAPB;
        const float BSCALE = 1023.0f / (1.0f - T0);
        int n = (int)n_raw;

        for (int i = tid; i < 1024; i += 256) hist[i] = 0;
        if (tid == 0) { cnt = 0; pivot = 0; }
        __syncthreads();

        for (int i = tid; i < n; i += 256) {
            unsigned long long k = BK[i];
            buf[i] = k;
            float s = __uint_as_float((unsigned)(k >> 32));
            int bin = (int)((s - T0) * BSCALE);
            bin = bin < 0 ? 0 : (bin > 1023 ? 1023 : bin);
            atomicAdd(&hist[bin], 1u);
        }
        __syncthreads();

        // exact pivot for rank KPRE: thread tid covers descending ranks [4t,4t+4)
        int lc[4];
        int local = 0;
#pragma unroll
        for (int k = 0; k < 4; k++) { lc[k] = (int)hist[1023 - (tid * 4 + k)]; local += lc[k]; }
        sscan[tid] = local;
        __syncthreads();
        for (int off = 1; off < 256; off <<= 1) {
            int vv = sscan[tid];
            int u = (tid >= off) ? sscan[tid - off] : 0;
            __syncthreads();
            sscan[tid] = vv + u;
            __syncthreads();
        }
        int incl = sscan[tid];
        int excl = incl - local;
        if (excl < KPRE && incl >= KPRE) {
            int run = excl;
#pragma unroll
            for (int k = 0; k < 4; k++) {
                run += lc[k];
                if (run >= KPRE) { pivot = 1023 - (tid * 4 + k); break; }
            }
        }
        __syncthreads();
        int P = pivot;

        if (n <= 1024) {
            // compact keys with bin >= P into buf[1024..1024+m)
            for (int i = tid; i < n; i += 256) {
                unsigned long long k = buf[i];
                float s = __uint_as_float((unsigned)(k >> 32));
                int bin = (int)((s - T0) * BSCALE);
                bin = bin < 0 ? 0 : (bin > 1023 ? 1023 : bin);
                if (bin >= P) {
                    unsigned pos = atomicAdd(&cnt, 1u);
                    buf[1024 + pos] = k;
                }
            }
            __syncthreads();
            int m = (int)cnt;
            int sp = SORTF;
            while (sp < m) sp <<= 1;       // 256/512/1024 (m <= n <= 1024)
            if (tid == 0) { soff = 1024; ssn = sp; }
            for (int i = tid; i < sp; i += 256)
                if (i >= m) buf[1024 + i] = 0ULL;
            __syncthreads();
        } else {
            if (tid == 0) { soff = 0; ssn = CAPB; }
            for (int i = tid; i < CAPB; i += 256)
                if (i >= n) buf[i] = 0ULL;
            __syncthreads();
        }
    } else {
        // ---- exact fallback: recompute row, hist-pivot over (0.25,1), collect ----
        float* row = g_fbrow + (size_t)bc * NA;
        const float FSCALE = 1023.0f / 0.75f;
        for (int i = tid; i < 1024; i += 256) hist[i] = 0;
        if (tid == 0) { cnt = 0; pivot = 0; }
        __syncthreads();

        for (int gi = tid; gi < NA; gi += 256) {
            int layer, g, xi, yi, sub;
            float ratio;
            const float* v = anchor_ptr(p5, p4, p3, b, gi, layer, g, ratio, xi, yi, sub);
            float conf = 1.f / (1.f + expf(-v[4]));
            float sc = conf * (1.f / (1.f + expf(-v[5 + c])));
            float s = (sc > SCORE_THR) ? sc : -1.f;
            row[gi] = s;
            if (s > 0.f) {
                int bin = (int)((s - SCORE_THR) * FSCALE);
                bin = bin < 0 ? 0 : (bin > 1023 ? 1023 : bin);
                atomicAdd(&hist[bin], 1u);
            }
        }
        __syncthreads();

        int lc[4];
        int local = 0;
#pragma unroll
        for (int k = 0; k < 4; k++) { lc[k] = (int)hist[1023 - (tid * 4 + k)]; local += lc[k]; }
        sscan[tid] = local;
        __syncthreads();
        for (int off = 1; off < 256; off <<= 1) {
            int vv = sscan[tid];
            int u = (tid >= off) ? sscan[tid - off] : 0;
            __syncthreads();
            sscan[tid] = vv + u;
            __syncthreads();
        }
        int incl = sscan[tid];
        int excl = incl - local;
        if (excl < KPRE && incl >= KPRE) {
            int run = excl;
#pragma unroll
            for (int k = 0; k < 4; k++) {
                run += lc[k];
                if (run >= KPRE) { pivot = 1023 - (tid * 4 + k); break; }
            }
        }
        __syncthreads();
        int P = pivot;

        for (int gi = tid; gi < NA; gi += 256) {
            float s = row[gi];
            if (s > 0.f) {
                int bin = (int)((s - SCORE_THR) * FSCALE);
                bin = bin < 0 ? 0 : (bin > 1023 ? 1023 : bin);
                if (bin >= P) {
                    unsigned pos = atomicAdd(&cnt, 1u);
                    if (pos < 1024)
                        buf[pos] = ((unsigned long long)__float_as_uint(s) << 32)
                                 | (unsigned)(0xFFFFFFFFu - (unsigned)gi);
                }
            }
        }
        __syncthreads();
        int m = cnt < 1024u ? (int)cnt : 1024;
        if (tid == 0) { soff = 0; ssn = 1024; }
        for (int i = tid; i < 1024; i += 256)
            if (i >= m) buf[i] = 0ULL;
        __syncthreads();
    }

    unsigned long long* sb = buf + soff;
    int sn = ssn;

    // bitonic sort descending
    for (int k = 2; k <= sn; k <<= 1) {
        for (int j = k >> 1; j > 0; j >>= 1) {
            for (int i = tid; i < sn; i += 256) {
                int ixj = i ^ j;
                if (ixj > i) {
                    unsigned long long A = sb[i], Bv = sb[ixj];
                    bool desc = ((i & k) == 0);
                    if (desc ? (A < Bv) : (A > Bv)) { sb[i] = Bv; sb[ixj] = A; }
                }
            }
            __syncthreads();
        }
    }

    // top-256 -> smem box arrays (R7-proven layout)
    unsigned long long key = sb[tid];
    bool valid = key != 0ULL;
    float sc;
    int a;
    if (valid) {
        sc = __uint_as_float((unsigned)(key >> 32));
        a = (int)(0xFFFFFFFFu - (unsigned)(key & 0xFFFFFFFFu));
    } else {
        sc = -1.f;
        a = 0;
    }
    float4 bb = valid ? g_boxes[b * NA + a] : make_float4(0.f, 0.f, 0.f, 0.f);
    bx1[tid] = bb.x; by1[tid] = bb.y; bx2[tid] = bb.z; by2[tid] = bb.w;
    float area = fmaxf(bb.z - bb.x, 0.f) * fmaxf(bb.w - bb.y, 0.f);
    barea[tid] = area;
    bscore[tid] = sc;
    banch[tid] = a;
    supp[tid] = valid ? 0 : 1;
    __syncthreads();

    // greedy NMS barrier loop (proven R7 form, exact ref IoU formula)
    float mx1 = bb.x, my1 = bb.y, mx2 = bb.z, my2 = bb.w, ma = area;
    bool msupp = !valid;
    for (int i = 0; i < KPRE - 1; i++) {
        if (!supp[i] && tid > i && !msupp) {
            float iw = fminf(mx2, bx2[i]) - fmaxf(mx1, bx1[i]);
            float ih = fminf(my2, by2[i]) - fmaxf(my1, by1[i]);
            iw = fmaxf(iw, 0.f);
            ih = fmaxf(ih, 0.f);
            float inter = iw * ih;
            float uni = ma + barea[i] - inter;
            float iou = inter / fmaxf(uni, 1e-9f);
            if (iou > IOU_THR) { msupp = true; supp[tid] = 1; }
        }
        __syncthreads();
    }

    // keep + cumsum cap at MAXB
    int keep = msupp ? 0 : 1;
    sscan[tid] = keep;
    __syncthreads();
    for (int off = 1; off < 256; off <<= 1) {
        int vv = sscan[tid];
        int u = (tid >= off) ? sscan[tid - off] : 0;
        __syncthreads();
        sscan[tid] = vv + u;
        __syncthreads();
    }
    int rank = sscan[tid];
    keep = keep && (rank <= MAXB);

    unsigned long long outkey = 0ULL;
    if (keep) {
        int flatpos = c * KPRE + tid;
        unsigned low = ((unsigned)(20479 - flatpos) << 15) | (unsigned)banch[tid];
        outkey = ((unsigned long long)__float_as_uint(bscore[tid]) << 32) | low;
    }
    g_keys[(size_t)b * NC * KPRE + c * KPRE + tid] = outkey;
}

// ---------------------------------------------------------------------------
// Pass 3: per-image top-100 (proven form)
// ---------------------------------------------------------------------------
__global__ __launch_bounds__(256) void final_kernel(float* __restrict__ out)
{
    __shared__ unsigned int hist[1024];
    __shared__ unsigned long long buf[SORTF];
    __shared__ int sscan[256];
    __shared__ unsigned int cnt;
    __shared__ int pivot;

    int b = blockIdx.x;
    int tid = threadIdx.x;
    const unsigned long long* K = g_keys + (size_t)b * NC * KPRE;
    const float FSCALE = 1023.0f / 0.75f;

    for (int i = tid; i < 1024; i += 256) hist[i] = 0;
    if (tid == 0) { cnt = 0; pivot = 0; }
    __syncthreads();

    for (int i = tid; i < NC * KPRE; i += 256) {
        unsigned long long k = K[i];
        if (k) {
            float s = __uint_as_float((unsigned)(k >> 32));
            int bin = (int)((s - SCORE_THR) * FSCALE);
            bin = bin < 0 ? 0 : (bin > 1023 ? 1023 : bin);
            atomicAdd(&hist[bin], 1u);
        }
    }
    __syncthreads();

    int lc[4];
    int local = 0;
#pragma unroll
    for (int kk = 0; kk < 4; kk++) { lc[kk] = (int)hist[1023 - (tid * 4 + kk)]; local += lc[kk]; }
    sscan[tid] = local;
    __syncthreads();
    for (int off = 1; off < 256; off <<= 1) {
        int vv = sscan[tid];
        int u = (tid >= off) ? sscan[tid - off] : 0;
        __syncthreads();
        sscan[tid] = vv + u;
        __syncthreads();
    }
    int incl = sscan[tid];
    int excl = incl - local;
    if (excl < MAXB && incl >= MAXB) {
        int run = excl;
#pragma unroll
        for (int kk = 0; kk < 4; kk++) {
            run += lc[kk];
            if (run >= MAXB) { pivot = 1023 - (tid * 4 + kk); break; }
        }
    }
    __syncthreads();
    int P = pivot;

    for (int i = tid; i < NC * KPRE; i += 256) {
        unsigned long long k = K[i];
        if (k) {
            float s = __uint_as_float((unsigned)(k >> 32));
            int bin = (int)((s - SCORE_THR) * FSCALE);
            bin = bin < 0 ? 0 : (bin > 1023 ? 1023 : bin);
            if (bin >= P) {
                unsigned pos = atomicAdd(&cnt, 1u);
                if (pos < SORTF) buf[pos] = k;
            }
        }
    }
    __syncthreads();
    int m = cnt < SORTF ? (int)cnt : SORTF;
    for (int i = tid; i < SORTF; i += 256)
        if (i >= m) buf[i] = 0ULL;
    __syncthreads();

    for (int k2 = 2; k2 <= SORTF; k2 <<= 1) {
        for (int j = k2 >> 1; j > 0; j >>= 1) {
            int ixj = tid ^ j;
            if (ixj > tid) {
                unsigned long long A = buf[tid], Bv = buf[ixj];
                bool desc = ((tid & k2) == 0);
                if (desc ? (A < Bv) : (A > Bv)) { buf[tid] = Bv; buf[ixj] = A; }
            }
            __syncthreads();
        }
    }

    if (tid < MAXB) {
        unsigned long long k = buf[tid];
        float x1 = -1.f, y1 = -1.f, x2 = -1.f, y2 = -1.f, scv = -1.f, lab = -1.f;
        if (k) {
            unsigned bits = (unsigned)(k >> 32);
            scv = __uint_as_float(bits);
            unsigned low = (unsigned)(k & 0xFFFFFFFFu);
            int flatpos = 20479 - (int)(low >> 15);
            int a = (int)(low & 0x7FFFu);
            int cls = flatpos >> 8;
            float4 bb = g_boxes[b * NA + a];
            x1 = bb.x; y1 = bb.y; x2 = bb.z; y2 = bb.w;
            lab = (float)cls;
        }
        float* ob = out;
        float* os = out + NB * MAXB * 4;
        float* ol = out + NB * MAXB * 5;
        ob[(b * MAXB + tid) * 4 + 0] = x1;
        ob[(b * MAXB + tid) * 4 + 1] = y1;
        ob[(b * MAXB + tid) * 4 + 2] = x2;
        ob[(b * MAXB + tid) * 4 + 3] = y2;
        os[b * MAXB + tid] = scv;
        ol[b * MAXB + tid] = lab;
    }
}

// ---------------------------------------------------------------------------
extern "C" void kernel_launch(void* const* d_in, const int* in_sizes, int n_in,
                              void* d_out, int out_size)
{
    const float* p5 = (const float*)d_in[0];
    const float* p4 = (const float*)d_in[1];
    const float* p3 = (const float*)d_in[2];
    float* out = (float*)d_out;

    init_kernel<<<(NB * NC + 255) / 256, 256>>>();
    decode_kernel<<<NB * DECBLK, 256>>>(p5, p4, p3);
    nms_kernel<<<NB * NC, 256>>>(p5, p4, p3);
    final_kernel<<<NB, 256>>>(out);
}

// round 11
// speedup vs baseline: 2.6835x; 1.1083x over previous
#include <cuda_runtime.h>
#include <math.h>
#include <stdint.h>

#define NB 16
#define NA 25200
#define NC 80
#define KPRE 256
#define MAXB 100
#define CAPB 2048
#define SORTF 256
#define SCORE_THR 0.25f
#define IOU_THR 0.1f
#define T0 0.58f

#define DECBLK 99   // ceil(25200/256) blocks per image

// anchors: p5 (20x20) [0,1200), p4 (40x40) [1200,6000), p3 (80x80) [6000,25200)

__device__ float4 g_boxes[NB * NA];
__device__ unsigned long long g_bucket[(size_t)NB * NC * CAPB];
__device__ unsigned int g_bcount[NB * NC];
__device__ float g_fbrow[(size_t)NB * NC * NA];   // fallback scratch only
__device__ unsigned long long g_keys[NB * NC * KPRE];

__constant__ float c_anch[9][2] = {
    {116.f, 90.f}, {156.f, 198.f}, {373.f, 326.f},
    {30.f, 61.f},  {62.f, 45.f},   {59.f, 119.f},
    {10.f, 13.f},  {16.f, 30.f},   {33.f, 23.f}
};

// ---------------------------------------------------------------------------
__global__ void init_kernel()
{
    int i = blockIdx.x * blockDim.x + threadIdx.x;
    if (i < NB * NC) g_bcount[i] = 0;
}

// ---------------------------------------------------------------------------
__device__ __forceinline__ const float* anchor_ptr(
    const float* p5, const float* p4, const float* p3,
    int b, int gi, int& layer, int& g, float& ratio, int& xi, int& yi, int& sub)
{
    const float* fm;
    int base;
    if (gi < 1200)      { layer = 0; base = 0;    g = 20; fm = p5; ratio = 32.f; }
    else if (gi < 6000) { layer = 1; base = 1200; g = 40; fm = p4; ratio = 16.f; }
    else                { layer = 2; base = 6000; g = 80; fm = p3; ratio = 8.f;  }
    int li = gi - base;
    int cell = li / 3;
    sub = li - cell * 3;
    xi = cell % g;
    yi = cell / g;
    return fm + ((size_t)(b * g + yi) * g + xi) * 255 + sub * 85;
}

__device__ __forceinline__ void scatter_key(int b, int c, float sc, int gi)
{
    int bkt = b * NC + c;
    unsigned pos = atomicAdd(&g_bcount[bkt], 1u);
    if (pos < CAPB)
        g_bucket[(size_t)bkt * CAPB + pos] =
            ((unsigned long long)__float_as_uint(sc) << 32)
            | (unsigned)(0xFFFFFFFFu - (unsigned)gi);
}

// ---------------------------------------------------------------------------
// Pass 1: decode boxes + T0 bucket scatter. Warp-cooperative class pass:
// a warp's 32 anchors are contiguous in memory (li*85 floats), so class
// logits are read coalesced; anchors with conf<=T0 are skipped entirely.
// ---------------------------------------------------------------------------
__global__ __launch_bounds__(256) void decode_kernel(
    const float* __restrict__ p5, const float* __restrict__ p4, const float* __restrict__ p3)
{
    int tid = threadIdx.x;
    int b = blockIdx.x / DECBLK;
    int blk = blockIdx.x - b * DECBLK;
    int lane = tid & 31;
    int warp_base = blk * 256 + (tid & ~31);
    int gi = warp_base + lane;

    int wl_first = warp_base < 1200 ? 0 : (warp_base < 6000 ? 1 : 2);
    int wl_lastgi = warp_base + 31;
    int wl_last = wl_lastgi < 1200 ? 0 : (wl_lastgi < 6000 ? 1 : 2);
    bool uniform = (wl_lastgi < NA) && (wl_first == wl_last);

    if (uniform) {
        const float* fm;
        int g, layerbase, arow;
        float ratio;
        if (wl_first == 0)      { fm = p5; g = 20; layerbase = 0;    arow = 0; ratio = 32.f; }
        else if (wl_first == 1) { fm = p4; g = 40; layerbase = 1200; arow = 3; ratio = 16.f; }
        else                    { fm = p3; g = 80; layerbase = 6000; arow = 6; ratio = 8.f;  }

        int li = gi - layerbase;
        int cell = li / 3;
        int sub = li - cell * 3;
        int xi = cell % g;
        int yi = cell / g;
        const float* v = fm + (size_t)b * g * g * 255 + (size_t)li * 85;

        float t0 = v[0], t1 = v[1], t2 = v[2], t3 = v[3], t4 = v[4];
        float sx = 1.f / (1.f + expf(-t0));
        float sy = 1.f / (1.f + expf(-t1));
        float cx = (sx + (float)xi) * ratio;
        float cy = (sy + (float)yi) * ratio;
        float w = expf(t2) * c_anch[arow + sub][0];
        float h = expf(t3) * c_anch[arow + sub][1];
        float conf = 1.f / (1.f + expf(-t4));

        g_boxes[b * NA + gi] = make_float4(cx - w * 0.5f, cy - h * 0.5f, cx + w * 0.5f, cy + h * 0.5f);

        float thr = __int_as_float(0x7F800000);
        if (conf > T0) {
            float q = T0 / conf;
            thr = logf(q / (1.f - q)) - 1e-3f;
        }

        // warp-cooperative class pass over the warp's 32 anchors
        const float* vbase = fm + (size_t)b * g * g * 255 + (size_t)(warp_base - layerbase) * 85;
        for (int al = 0; al < 32; al++) {
            float thr_a = __shfl_sync(0xFFFFFFFFu, thr, al);
            if (thr_a < 1e37f) {                         // conf_a > T0: anchor can pass
                float conf_a = __shfl_sync(0xFFFFFFFFu, conf, al);
                const float* va = vbase + al * 85 + 5;
                int gia = warp_base + al;
#pragma unroll
                for (int r = 0; r < 3; r++) {
                    int c = lane + r * 32;
                    if (c < NC) {
                        float xc = va[c];                // coalesced across lanes
                        if (xc > thr_a) {
                            float sc = conf_a * (1.f / (1.f + expf(-xc)));   // identical math
                            if (sc >= T0) scatter_key(b, c, sc, gia);
                        }
                    }
                }
            }
        }
    } else {
        // boundary / tail warps: per-thread path (R7-proven)
        if (gi >= NA) return;

        int layer, g, xi, yi, sub;
        float ratio;
        const float* v = anchor_ptr(p5, p4, p3, b, gi, layer, g, ratio, xi, yi, sub);

        float t0 = v[0], t1 = v[1], t2 = v[2], t3 = v[3], t4 = v[4];
        float sx = 1.f / (1.f + expf(-t0));
        float sy = 1.f / (1.f + expf(-t1));
        float cx = (sx + (float)xi) * ratio;
        float cy = (sy + (float)yi) * ratio;
        float w = expf(t2) * c_anch[layer * 3 + sub][0];
        float h = expf(t3) * c_anch[layer * 3 + sub][1];
        float conf = 1.f / (1.f + expf(-t4));

        g_boxes[b * NA + gi] = make_float4(cx - w * 0.5f, cy - h * 0.5f, cx + w * 0.5f, cy + h * 0.5f);

        float thr = __int_as_float(0x7F800000);
        if (conf > T0) {
            float q = T0 / conf;
            thr = logf(q / (1.f - q)) - 1e-3f;
        }

#pragma unroll
        for (int c = 0; c < NC; c++) {
            float xc = v[5 + c];
            if (xc > thr) {
                float sc = conf * (1.f / (1.f + expf(-xc)));
                if (sc >= T0) scatter_key(b, c, sc, gi);
            }
        }
    }
}

// ---------------------------------------------------------------------------
// Pass 2: prune (hist pivot -> compact) -> small bitonic sort -> barrier NMS
// (byte-identical to the passing 360us R10 version)
// ---------------------------------------------------------------------------
__global__ __launch_bounds__(256) void nms_kernel(
    const float* __restrict__ p5, const float* __restrict__ p4, const float* __restrict__ p3)
{
    __shared__ unsigned long long buf[CAPB];   // 16 KB
    __shared__ unsigned int hist[1024];        // 4 KB
    __shared__ int sscan[256];
    __shared__ unsigned int cnt;
    __shared__ int pivot;
    __shared__ int soff, ssn;
    __shared__ float bx1[KPRE], by1[KPRE], bx2[KPRE], by2[KPRE], barea[KPRE], bscore[KPRE];
    __shared__ int banch[KPRE];
    __shared__ int supp[KPRE];

    int bc = blockIdx.x;
    int b = bc / NC;
    int c = bc - b * NC;
    int tid = threadIdx.x;

    unsigned n_raw = g_bcount[bc];

    if (n_raw >= KPRE && n_raw <= CAPB) {
        const unsigned long long* BK = g_bucket + (size_t)bc * CAPB;
        const float BSCALE = 1023.0f / (1.0f - T0);
        int n = (int)n_raw;

        for (int i = tid; i < 1024; i += 256) hist[i] = 0;
        if (tid == 0) { cnt = 0; pivot = 0; }
        __syncthreads();

        for (int i = tid; i < n; i += 256) {
            unsigned long long k = BK[i];
            buf[i] = k;
            float s = __uint_as_float((unsigned)(k >> 32));
            int bin = (int)((s - T0) * BSCALE);
            bin = bin < 0 ? 0 : (bin > 1023 ? 1023 : bin);
            atomicAdd(&hist[bin], 1u);
        }
        __syncthreads();

        int lc[4];
        int local = 0;
#pragma unroll
        for (int k = 0; k < 4; k++) { lc[k] = (int)hist[1023 - (tid * 4 + k)]; local += lc[k]; }
        sscan[tid] = local;
        __syncthreads();
        for (int off = 1; off < 256; off <<= 1) {
            int vv = sscan[tid];
            int u = (tid >= off) ? sscan[tid - off] : 0;
            __syncthreads();
            sscan[tid] = vv + u;
            __syncthreads();
        }
        int incl = sscan[tid];
        int excl = incl - local;
        if (excl < KPRE && incl >= KPRE) {
            int run = excl;
#pragma unroll
            for (int k = 0; k < 4; k++) {
                run += lc[k];
                if (run >= KPRE) { pivot = 1023 - (tid * 4 + k); break; }
            }
        }
        __syncthreads();
        int P = pivot;

        if (n <= 1024) {
            for (int i = tid; i < n; i += 256) {
                unsigned long long k = buf[i];
                float s = __uint_as_float((unsigned)(k >> 32));
                int bin = (int)((s - T0) * BSCALE);
                bin = bin < 0 ? 0 : (bin > 1023 ? 1023 : bin);
                if (bin >= P) {
                    unsigned pos = atomicAdd(&cnt, 1u);
                    buf[1024 + pos] = k;
                }
            }
            __syncthreads();
            int m = (int)cnt;
            int sp = SORTF;
            while (sp < m) sp <<= 1;
            if (tid == 0) { soff = 1024; ssn = sp; }
            for (int i = tid; i < sp; i += 256)
                if (i >= m) buf[1024 + i] = 0ULL;
            __syncthreads();
        } else {
            if (tid == 0) { soff = 0; ssn = CAPB; }
            for (int i = tid; i < CAPB; i += 256)
                if (i >= n) buf[i] = 0ULL;
            __syncthreads();
        }
    } else {
        // exact fallback: recompute row, hist-pivot over (0.25,1), collect
        float* row = g_fbrow + (size_t)bc * NA;
        const float FSCALE = 1023.0f / 0.75f;
        for (int i = tid; i < 1024; i += 256) hist[i] = 0;
        if (tid == 0) { cnt = 0; pivot = 0; }
        __syncthreads();

        for (int gi = tid; gi < NA; gi += 256) {
            int layer, g, xi, yi, sub;
            float ratio;
            const float* v = anchor_ptr(p5, p4, p3, b, gi, layer, g, ratio, xi, yi, sub);
            float conf = 1.f / (1.f + expf(-v[4]));
            float sc = conf * (1.f / (1.f + expf(-v[5 + c])));
            float s = (sc > SCORE_THR) ? sc : -1.f;
            row[gi] = s;
            if (s > 0.f) {
                int bin = (int)((s - SCORE_THR) * FSCALE);
                bin = bin < 0 ? 0 : (bin > 1023 ? 1023 : bin);
                atomicAdd(&hist[bin], 1u);
            }
        }
        __syncthreads();

        int lc[4];
        int local = 0;
#pragma unroll
        for (int k = 0; k < 4; k++) { lc[k] = (int)hist[1023 - (tid * 4 + k)]; local += lc[k]; }
        sscan[tid] = local;
        __syncthreads();
        for (int off = 1; off < 256; off <<= 1) {
            int vv = sscan[tid];
            int u = (tid >= off) ? sscan[tid - off] : 0;
            __syncthreads();
            sscan[tid] = vv + u;
            __syncthreads();
        }
        int incl = sscan[tid];
        int excl = incl - local;
        if (excl < KPRE && incl >= KPRE) {
            int run = excl;
#pragma unroll
            for (int k = 0; k < 4; k++) {
                run += lc[k];
                if (run >= KPRE) { pivot = 1023 - (tid * 4 + k); break; }
            }
        }
        __syncthreads();
        int P = pivot;

        for (int gi = tid; gi < NA; gi += 256) {
            float s = row[gi];
            if (s > 0.f) {
                int bin = (int)((s - SCORE_THR) * FSCALE);
                bin = bin < 0 ? 0 : (bin > 1023 ? 1023 : bin);
                if (bin >= P) {
                    unsigned pos = atomicAdd(&cnt, 1u);
                    if (pos < 1024)
                        buf[pos] = ((unsigned long long)__float_as_uint(s) << 32)
                                 | (unsigned)(0xFFFFFFFFu - (unsigned)gi);
                }
            }
        }
        __syncthreads();
        int m = cnt < 1024u ? (int)cnt : 1024;
        if (tid == 0) { soff = 0; ssn = 1024; }
        for (int i = tid; i < 1024; i += 256)
            if (i >= m) buf[i] = 0ULL;
        __syncthreads();
    }

    unsigned long long* sb = buf + soff;
    int sn = ssn;

    for (int k = 2; k <= sn; k <<= 1) {
        for (int j = k >> 1; j > 0; j >>= 1) {
            for (int i = tid; i < sn; i += 256) {
                int ixj = i ^ j;
                if (ixj > i) {
                    unsigned long long A = sb[i], Bv = sb[ixj];
                    bool desc = ((i & k) == 0);
                    if (desc ? (A < Bv) : (A > Bv)) { sb[i] = Bv; sb[ixj] = A; }
                }
            }
            __syncthreads();
        }
    }

    unsigned long long key = sb[tid];
    bool valid = key != 0ULL;
    float sc;
    int a;
    if (valid) {
        sc = __uint_as_float((unsigned)(key >> 32));
        a = (int)(0xFFFFFFFFu - (unsigned)(key & 0xFFFFFFFFu));
    } else {
        sc = -1.f;
        a = 0;
    }
    float4 bb = valid ? g_boxes[b * NA + a] : make_float4(0.f, 0.f, 0.f, 0.f);
    bx1[tid] = bb.x; by1[tid] = bb.y; bx2[tid] = bb.z; by2[tid] = bb.w;
    float area = fmaxf(bb.z - bb.x, 0.f) * fmaxf(bb.w - bb.y, 0.f);
    barea[tid] = area;
    bscore[tid] = sc;
    banch[tid] = a;
    supp[tid] = valid ? 0 : 1;
    __syncthreads();

    float mx1 = bb.x, my1 = bb.y, mx2 = bb.z, my2 = bb.w, ma = area;
    bool msupp = !valid;
    for (int i = 0; i < KPRE - 1; i++) {
        if (!supp[i] && tid > i && !msupp) {
            float iw = fminf(mx2, bx2[i]) - fmaxf(mx1, bx1[i]);
            float ih = fminf(my2, by2[i]) - fmaxf(my1, by1[i]);
            iw = fmaxf(iw, 0.f);
            ih = fmaxf(ih, 0.f);
            float inter = iw * ih;
            float uni = ma + barea[i] - inter;
            float iou = inter / fmaxf(uni, 1e-9f);
            if (iou > IOU_THR) { msupp = true; supp[tid] = 1; }
        }
        __syncthreads();
    }

    int keep = msupp ? 0 : 1;
    sscan[tid] = keep;
    __syncthreads();
    for (int off = 1; off < 256; off <<= 1) {
        int vv = sscan[tid];
        int u = (tid >= off) ? sscan[tid - off] : 0;
        __syncthreads();
        sscan[tid] = vv + u;
        __syncthreads();
    }
    int rank = sscan[tid];
    keep = keep && (rank <= MAXB);

    unsigned long long outkey = 0ULL;
    if (keep) {
        int flatpos = c * KPRE + tid;
        unsigned low = ((unsigned)(20479 - flatpos) << 15) | (unsigned)banch[tid];
        outkey = ((unsigned long long)__float_as_uint(bscore[tid]) << 32) | low;
    }
    g_keys[(size_t)b * NC * KPRE + c * KPRE + tid] = outkey;
}

// ---------------------------------------------------------------------------
// Pass 3: per-image top-100 (byte-identical to R10)
// ---------------------------------------------------------------------------
__global__ __launch_bounds__(256) void final_kernel(float* __restrict__ out)
{
    __shared__ unsigned int hist[1024];
    __shared__ unsigned long long buf[SORTF];
    __shared__ int sscan[256];
    __shared__ unsigned int cnt;
    __shared__ int pivot;

    int b = blockIdx.x;
    int tid = threadIdx.x;
    const unsigned long long* K = g_keys + (size_t)b * NC * KPRE;
    const float FSCALE = 1023.0f / 0.75f;

    for (int i = tid; i < 1024; i += 256) hist[i] = 0;
    if (tid == 0) { cnt = 0; pivot = 0; }
    __syncthreads();

    for (int i = tid; i < NC * KPRE; i += 256) {
        unsigned long long k = K[i];
        if (k) {
            float s = __uint_as_float((unsigned)(k >> 32));
            int bin = (int)((s - SCORE_THR) * FSCALE);
            bin = bin < 0 ? 0 : (bin > 1023 ? 1023 : bin);
            atomicAdd(&hist[bin], 1u);
        }
    }
    __syncthreads();

    int lc[4];
    int local = 0;
#pragma unroll
    for (int kk = 0; kk < 4; kk++) { lc[kk] = (int)hist[1023 - (tid * 4 + kk)]; local += lc[kk]; }
    sscan[tid] = local;
    __syncthreads();
    for (int off = 1; off < 256; off <<= 1) {
        int vv = sscan[tid];
        int u = (tid >= off) ? sscan[tid - off] : 0;
        __syncthreads();
        sscan[tid] = vv + u;
        __syncthreads();
    }
    int incl = sscan[tid];
    int excl = incl - local;
    if (excl < MAXB && incl >= MAXB) {
        int run = excl;
#pragma unroll
        for (int kk = 0; kk < 4; kk++) {
            run += lc[kk];
            if (run >= MAXB) { pivot = 1023 - (tid * 4 + kk); break; }
        }
    }
    __syncthreads();
    int P = pivot;

    for (int i = tid; i < NC * KPRE; i += 256) {
        unsigned long long k = K[i];
        if (k) {
            float s = __uint_as_float((unsigned)(k >> 32));
            int bin = (int)((s - SCORE_THR) * FSCALE);
            bin = bin < 0 ? 0 : (bin > 1023 ? 1023 : bin);
            if (bin >= P) {
                unsigned pos = atomicAdd(&cnt, 1u);
                if (pos < SORTF) buf[pos] = k;
            }
        }
    }
    __syncthreads();
    int m = cnt < SORTF ? (int)cnt : SORTF;
    for (int i = tid; i < SORTF; i += 256)
        if (i >= m) buf[i] = 0ULL;
    __syncthreads();

    for (int k2 = 2; k2 <= SORTF; k2 <<= 1) {
        for (int j = k2 >> 1; j > 0; j >>= 1) {
            int ixj = tid ^ j;
            if (ixj > tid) {
                unsigned long long A = buf[tid], Bv = buf[ixj];
                bool desc = ((tid & k2) == 0);
                if (desc ? (A < Bv) : (A > Bv)) { buf[tid] = Bv; buf[ixj] = A; }
            }
            __syncthreads();
        }
    }

    if (tid < MAXB) {
        unsigned long long k = buf[tid];
        float x1 = -1.f, y1 = -1.f, x2 = -1.f, y2 = -1.f, scv = -1.f, lab = -1.f;
        if (k) {
            unsigned bits = (unsigned)(k >> 32);
            scv = __uint_as_float(bits);
            unsigned low = (unsigned)(k & 0xFFFFFFFFu);
            int flatpos = 20479 - (int)(low >> 15);
            int a = (int)(low & 0x7FFFu);
            int cls = flatpos >> 8;
            float4 bb = g_boxes[b * NA + a];
            x1 = bb.x; y1 = bb.y; x2 = bb.z; y2 = bb.w;
            lab = (float)cls;
        }
        float* ob = out;
        float* os = out + NB * MAXB * 4;
        float* ol = out + NB * MAXB * 5;
        ob[(b * MAXB + tid) * 4 + 0] = x1;
        ob[(b * MAXB + tid) * 4 + 1] = y1;
        ob[(b * MAXB + tid) * 4 + 2] = x2;
        ob[(b * MAXB + tid) * 4 + 3] = y2;
        os[b * MAXB + tid] = scv;
        ol[b * MAXB + tid] = lab;
    }
}

// ---------------------------------------------------------------------------
extern "C" void kernel_launch(void* const* d_in, const int* in_sizes, int n_in,
                              void* d_out, int out_size)
{
    const float* p5 = (const float*)d_in[0];
    const float* p4 = (const float*)d_in[1];
    const float* p3 = (const float*)d_in[2];
    float* out = (float*)d_out;

    init_kernel<<<(NB * NC + 255) / 256, 256>>>();
    decode_kernel<<<NB * DECBLK, 256>>>(p5, p4, p3);
    nms_kernel<<<NB * NC, 256>>>(p5, p4, p3);
    final_kernel<<<NB, 256>>>(out);
}

// round 12
// speedup vs baseline: 3.1523x; 1.1747x over previous
#include <cuda_runtime.h>
#include <math.h>
#include <stdint.h>

#define NB 16
#define NA 25200
#define NC 80
#define KPRE 256
#define MAXB 100
#define CAPB 2048
#define SORTF 256
#define SCORE_THR 0.25f
#define IOU_THR 0.1f
#define T0 0.58f

#define DECBLK 99   // ceil(25200/256) blocks per image

// anchors: p5 (20x20) [0,1200), p4 (40x40) [1200,6000), p3 (80x80) [6000,25200)

__device__ float4 g_boxes[NB * NA];
__device__ unsigned long long g_bucket[(size_t)NB * NC * CAPB];
__device__ unsigned int g_bcount[NB * NC];          // zero-init at load; re-zeroed by nms
__device__ float g_fbrow[(size_t)NB * NC * NA];     // fallback scratch only
__device__ unsigned long long g_keys[NB * NC * KPRE];

__constant__ float c_anch[9][2] = {
    {116.f, 90.f}, {156.f, 198.f}, {373.f, 326.f},
    {30.f, 61.f},  {62.f, 45.f},   {59.f, 119.f},
    {10.f, 13.f},  {16.f, 30.f},   {33.f, 23.f}
};

// ---------------------------------------------------------------------------
__device__ __forceinline__ const float* anchor_ptr(
    const float* p5, const float* p4, const float* p3,
    int b, int gi, int& layer, int& g, float& ratio, int& xi, int& yi, int& sub)
{
    const float* fm;
    int base;
    if (gi < 1200)      { layer = 0; base = 0;    g = 20; fm = p5; ratio = 32.f; }
    else if (gi < 6000) { layer = 1; base = 1200; g = 40; fm = p4; ratio = 16.f; }
    else                { layer = 2; base = 6000; g = 80; fm = p3; ratio = 8.f;  }
    int li = gi - base;
    int cell = li / 3;
    sub = li - cell * 3;
    xi = cell % g;
    yi = cell / g;
    return fm + ((size_t)(b * g + yi) * g + xi) * 255 + sub * 85;
}

__device__ __forceinline__ void scatter_key(int b, int c, float sc, int gi)
{
    int bkt = b * NC + c;
    unsigned pos = atomicAdd(&g_bcount[bkt], 1u);
    if (pos < CAPB)
        g_bucket[(size_t)bkt * CAPB + pos] =
            ((unsigned long long)__float_as_uint(sc) << 32)
            | (unsigned)(0xFFFFFFFFu - (unsigned)gi);
}

// ---------------------------------------------------------------------------
// Pass 1: decode boxes + T0 bucket scatter (byte-identical to passing R11)
// ---------------------------------------------------------------------------
__global__ __launch_bounds__(256) void decode_kernel(
    const float* __restrict__ p5, const float* __restrict__ p4, const float* __restrict__ p3)
{
    int tid = threadIdx.x;
    int b = blockIdx.x / DECBLK;
    int blk = blockIdx.x - b * DECBLK;
    int lane = tid & 31;
    int warp_base = blk * 256 + (tid & ~31);
    int gi = warp_base + lane;

    int wl_first = warp_base < 1200 ? 0 : (warp_base < 6000 ? 1 : 2);
    int wl_lastgi = warp_base + 31;
    int wl_last = wl_lastgi < 1200 ? 0 : (wl_lastgi < 6000 ? 1 : 2);
    bool uniform = (wl_lastgi < NA) && (wl_first == wl_last);

    if (uniform) {
        const float* fm;
        int g, layerbase, arow;
        float ratio;
        if (wl_first == 0)      { fm = p5; g = 20; layerbase = 0;    arow = 0; ratio = 32.f; }
        else if (wl_first == 1) { fm = p4; g = 40; layerbase = 1200; arow = 3; ratio = 16.f; }
        else                    { fm = p3; g = 80; layerbase = 6000; arow = 6; ratio = 8.f;  }

        int li = gi - layerbase;
        int cell = li / 3;
        int sub = li - cell * 3;
        int xi = cell % g;
        int yi = cell / g;
        const float* v = fm + (size_t)b * g * g * 255 + (size_t)li * 85;

        float t0 = v[0], t1 = v[1], t2 = v[2], t3 = v[3], t4 = v[4];
        float sx = 1.f / (1.f + expf(-t0));
        float sy = 1.f / (1.f + expf(-t1));
        float cx = (sx + (float)xi) * ratio;
        float cy = (sy + (float)yi) * ratio;
        float w = expf(t2) * c_anch[arow + sub][0];
        float h = expf(t3) * c_anch[arow + sub][1];
        float conf = 1.f / (1.f + expf(-t4));

        g_boxes[b * NA + gi] = make_float4(cx - w * 0.5f, cy - h * 0.5f, cx + w * 0.5f, cy + h * 0.5f);

        float thr = __int_as_float(0x7F800000);
        if (conf > T0) {
            float q = T0 / conf;
            thr = logf(q / (1.f - q)) - 1e-3f;
        }

        const float* vbase = fm + (size_t)b * g * g * 255 + (size_t)(warp_base - layerbase) * 85;
        for (int al = 0; al < 32; al++) {
            float thr_a = __shfl_sync(0xFFFFFFFFu, thr, al);
            if (thr_a < 1e37f) {
                float conf_a = __shfl_sync(0xFFFFFFFFu, conf, al);
                const float* va = vbase + al * 85 + 5;
                int gia = warp_base + al;
#pragma unroll
                for (int r = 0; r < 3; r++) {
                    int c = lane + r * 32;
                    if (c < NC) {
                        float xc = va[c];
                        if (xc > thr_a) {
                            float sc = conf_a * (1.f / (1.f + expf(-xc)));
                            if (sc >= T0) scatter_key(b, c, sc, gia);
                        }
                    }
                }
            }
        }
    } else {
        if (gi >= NA) return;

        int layer, g, xi, yi, sub;
        float ratio;
        const float* v = anchor_ptr(p5, p4, p3, b, gi, layer, g, ratio, xi, yi, sub);

        float t0 = v[0], t1 = v[1], t2 = v[2], t3 = v[3], t4 = v[4];
        float sx = 1.f / (1.f + expf(-t0));
        float sy = 1.f / (1.f + expf(-t1));
        float cx = (sx + (float)xi) * ratio;
        float cy = (sy + (float)yi) * ratio;
        float w = expf(t2) * c_anch[layer * 3 + sub][0];
        float h = expf(t3) * c_anch[layer * 3 + sub][1];
        float conf = 1.f / (1.f + expf(-t4));

        g_boxes[b * NA + gi] = make_float4(cx - w * 0.5f, cy - h * 0.5f, cx + w * 0.5f, cy + h * 0.5f);

        float thr = __int_as_float(0x7F800000);
        if (conf > T0) {
            float q = T0 / conf;
            thr = logf(q / (1.f - q)) - 1e-3f;
        }

#pragma unroll
        for (int c = 0; c < NC; c++) {
            float xc = v[5 + c];
            if (xc > thr) {
                float sc = conf * (1.f / (1.f + expf(-xc)));
                if (sc >= T0) scatter_key(b, c, sc, gi);
            }
        }
    }
}

// ---------------------------------------------------------------------------
// Pass 2: prune -> small bitonic sort -> barrier NMS with early exit
// ---------------------------------------------------------------------------
__global__ __launch_bounds__(256) void nms_kernel(
    const float* __restrict__ p5, const float* __restrict__ p4, const float* __restrict__ p3)
{
    __shared__ unsigned long long buf[CAPB];   // 16 KB
    __shared__ unsigned int hist[1024];        // 4 KB
    __shared__ int sscan[256];                 // scans (fallback) / warp sums (fast)
    __shared__ unsigned int cnt;
    __shared__ int pivot;
    __shared__ int soff, ssn;
    __shared__ float bx1[KPRE], by1[KPRE], bx2[KPRE], by2[KPRE], barea[KPRE], bscore[KPRE];
    __shared__ int banch[KPRE];
    __shared__ int supp[KPRE];
    __shared__ unsigned int kwarp[8];

    int bc = blockIdx.x;
    int b = bc / NC;
    int c = bc - b * NC;
    int tid = threadIdx.x;
    int lane = tid & 31;
    int wid = tid >> 5;

    unsigned n_raw = g_bcount[bc];

    if (n_raw >= KPRE && n_raw <= CAPB) {
        // ---- fast path: load keys + histogram scores ----
        const unsigned long long* BK = g_bucket + (size_t)bc * CAPB;
        const float BSCALE = 1023.0f / (1.0f - T0);
        int n = (int)n_raw;

        for (int i = tid; i < 1024; i += 256) hist[i] = 0;
        if (tid == 0) { cnt = 0; pivot = 0; }
        __syncthreads();

        for (int i = tid; i < n; i += 256) {
            unsigned long long k = BK[i];
            buf[i] = k;
            float s = __uint_as_float((unsigned)(k >> 32));
            int bin = (int)((s - T0) * BSCALE);
            bin = bin < 0 ? 0 : (bin > 1023 ? 1023 : bin);
            atomicAdd(&hist[bin], 1u);
        }
        __syncthreads();

        // exact pivot for rank KPRE via shfl scan (1 barrier)
        int lc[4];
        int local = 0;
#pragma unroll
        for (int k = 0; k < 4; k++) { lc[k] = (int)hist[1023 - (tid * 4 + k)]; local += lc[k]; }
        int x = local;
#pragma unroll
        for (int d = 1; d < 32; d <<= 1) {
            int y = __shfl_up_sync(0xFFFFFFFFu, x, d);
            if (lane >= d) x += y;
        }
        if (lane == 31) sscan[wid] = x;      // warp totals in sscan[0..7]
        __syncthreads();
        int off = 0;
        for (int w = 0; w < wid; w++) off += sscan[w];
        int incl = x + off;
        int excl = incl - local;
        if (excl < KPRE && incl >= KPRE) {
            int run = excl;
#pragma unroll
            for (int k = 0; k < 4; k++) {
                run += lc[k];
                if (run >= KPRE) { pivot = 1023 - (tid * 4 + k); break; }
            }
        }
        __syncthreads();
        int P = pivot;

        if (n <= 1024) {
            for (int i = tid; i < n; i += 256) {
                unsigned long long k = buf[i];
                float s = __uint_as_float((unsigned)(k >> 32));
                int bin = (int)((s - T0) * BSCALE);
                bin = bin < 0 ? 0 : (bin > 1023 ? 1023 : bin);
                if (bin >= P) {
                    unsigned pos = atomicAdd(&cnt, 1u);
                    buf[1024 + pos] = k;
                }
            }
            __syncthreads();
            int m = (int)cnt;
            int sp = SORTF;
            while (sp < m) sp <<= 1;
            if (tid == 0) { soff = 1024; ssn = sp; }
            for (int i = tid; i < sp; i += 256)
                if (i >= m) buf[1024 + i] = 0ULL;
            __syncthreads();
        } else {
            if (tid == 0) { soff = 0; ssn = CAPB; }
            for (int i = tid; i < CAPB; i += 256)
                if (i >= n) buf[i] = 0ULL;
            __syncthreads();
        }
    } else {
        // ---- exact fallback (proven R10 code, never taken for this seed) ----
        float* row = g_fbrow + (size_t)bc * NA;
        const float FSCALE = 1023.0f / 0.75f;
        for (int i = tid; i < 1024; i += 256) hist[i] = 0;
        if (tid == 0) { cnt = 0; pivot = 0; }
        __syncthreads();

        for (int gi = tid; gi < NA; gi += 256) {
            int layer, g, xi, yi, sub;
            float ratio;
            const float* v = anchor_ptr(p5, p4, p3, b, gi, layer, g, ratio, xi, yi, sub);
            float conf = 1.f / (1.f + expf(-v[4]));
            float sc = conf * (1.f / (1.f + expf(-v[5 + c])));
            float s = (sc > SCORE_THR) ? sc : -1.f;
            row[gi] = s;
            if (s > 0.f) {
                int bin = (int)((s - SCORE_THR) * FSCALE);
                bin = bin < 0 ? 0 : (bin > 1023 ? 1023 : bin);
                atomicAdd(&hist[bin], 1u);
            }
        }
        __syncthreads();

        int lc[4];
        int local = 0;
#pragma unroll
        for (int k = 0; k < 4; k++) { lc[k] = (int)hist[1023 - (tid * 4 + k)]; local += lc[k]; }
        sscan[tid] = local;
        __syncthreads();
        for (int off2 = 1; off2 < 256; off2 <<= 1) {
            int vv = sscan[tid];
            int u = (tid >= off2) ? sscan[tid - off2] : 0;
            __syncthreads();
            sscan[tid] = vv + u;
            __syncthreads();
        }
        int incl = sscan[tid];
        int excl = incl - local;
        if (excl < KPRE && incl >= KPRE) {
            int run = excl;
#pragma unroll
            for (int k = 0; k < 4; k++) {
                run += lc[k];
                if (run >= KPRE) { pivot = 1023 - (tid * 4 + k); break; }
            }
        }
        __syncthreads();
        int P = pivot;

        for (int gi = tid; gi < NA; gi += 256) {
            float s = row[gi];
            if (s > 0.f) {
                int bin = (int)((s - SCORE_THR) * FSCALE);
                bin = bin < 0 ? 0 : (bin > 1023 ? 1023 : bin);
                if (bin >= P) {
                    unsigned pos = atomicAdd(&cnt, 1u);
                    if (pos < 1024)
                        buf[pos] = ((unsigned long long)__float_as_uint(s) << 32)
                                 | (unsigned)(0xFFFFFFFFu - (unsigned)gi);
                }
            }
        }
        __syncthreads();
        int m = cnt < 1024u ? (int)cnt : 1024;
        if (tid == 0) { soff = 0; ssn = 1024; }
        for (int i = tid; i < 1024; i += 256)
            if (i >= m) buf[i] = 0ULL;
        __syncthreads();
    }

    unsigned long long* sb = buf + soff;
    int sn = ssn;

    // bitonic sort descending
    for (int k = 2; k <= sn; k <<= 1) {
        for (int j = k >> 1; j > 0; j >>= 1) {
            for (int i = tid; i < sn; i += 256) {
                int ixj = i ^ j;
                if (ixj > i) {
                    unsigned long long A = sb[i], Bv = sb[ixj];
                    bool desc = ((i & k) == 0);
                    if (desc ? (A < Bv) : (A > Bv)) { sb[i] = Bv; sb[ixj] = A; }
                }
            }
            __syncthreads();
        }
    }

    // top-256 -> smem box arrays
    unsigned long long key = sb[tid];
    bool valid = key != 0ULL;
    float sc;
    int a;
    if (valid) {
        sc = __uint_as_float((unsigned)(key >> 32));
        a = (int)(0xFFFFFFFFu - (unsigned)(key & 0xFFFFFFFFu));
    } else {
        sc = -1.f;
        a = 0;
    }
    float4 bb = valid ? g_boxes[b * NA + a] : make_float4(0.f, 0.f, 0.f, 0.f);
    bx1[tid] = bb.x; by1[tid] = bb.y; bx2[tid] = bb.z; by2[tid] = bb.w;
    float area = fmaxf(bb.z - bb.x, 0.f) * fmaxf(bb.w - bb.y, 0.f);
    barea[tid] = area;
    bscore[tid] = sc;
    banch[tid] = a;
    supp[tid] = valid ? 0 : 1;
    __syncthreads();

    // greedy NMS barrier loop with early exit at MAXB keeps.
    // Invariant: supp[i] is final at iteration i. Once the 100th keep is seen,
    // every later box has inclusive rank >= 101 and is dropped by the cap, and
    // its suppression only affects later boxes -> break (uniform across block).
    float mx1 = bb.x, my1 = bb.y, mx2 = bb.z, my2 = bb.w, ma = area;
    bool msupp = !valid;
    int kept_cnt = 0;
    for (int i = 0; i < KPRE - 1; i++) {
        int supp_i = supp[i];
        if (!supp_i) {
            kept_cnt++;
            if (kept_cnt >= MAXB) break;
            if (tid > i && !msupp) {
                float iw = fminf(mx2, bx2[i]) - fmaxf(mx1, bx1[i]);
                float ih = fminf(my2, by2[i]) - fmaxf(my1, by1[i]);
                iw = fmaxf(iw, 0.f);
                ih = fmaxf(ih, 0.f);
                float inter = iw * ih;
                float uni = ma + barea[i] - inter;
                float iou = inter / fmaxf(uni, 1e-9f);
                if (iou > IOU_THR) { msupp = true; supp[tid] = 1; }
            }
        }
        __syncthreads();
    }
    __syncthreads();   // ensure last-iteration supp writes visible everywhere

    // keep + rank via ballot (1 barrier)
    bool keep = !msupp;
    unsigned kb = __ballot_sync(0xFFFFFFFFu, keep);
    if (lane == 0) kwarp[wid] = kb;
    __syncthreads();
    if (keep) {
        int rank = __popc(kb & (0xFFFFFFFFu >> (31 - lane)));
        for (int w = 0; w < wid; w++) rank += __popc(kwarp[w]);
        keep = rank <= MAXB;
    }

    unsigned long long outkey = 0ULL;
    if (keep) {
        int flatpos = c * KPRE + tid;
        unsigned low = ((unsigned)(20479 - flatpos) << 15) | (unsigned)banch[tid];
        outkey = ((unsigned long long)__float_as_uint(bscore[tid]) << 32) | low;
    }
    g_keys[(size_t)b * NC * KPRE + c * KPRE + tid] = outkey;

    // reset bucket counter for the next graph replay (replaces init_kernel)
    if (tid == 0) g_bcount[bc] = 0;
}

// ---------------------------------------------------------------------------
// Pass 3: per-image top-100 (byte-identical to R10/R11)
// ---------------------------------------------------------------------------
__global__ __launch_bounds__(256) void final_kernel(float* __restrict__ out)
{
    __shared__ unsigned int hist[1024];
    __shared__ unsigned long long buf[SORTF];
    __shared__ int sscan[256];
    __shared__ unsigned int cnt;
    __shared__ int pivot;

    int b = blockIdx.x;
    int tid = threadIdx.x;
    const unsigned long long* K = g_keys + (size_t)b * NC * KPRE;
    const float FSCALE = 1023.0f / 0.75f;

    for (int i = tid; i < 1024; i += 256) hist[i] = 0;
    if (tid == 0) { cnt = 0; pivot = 0; }
    __syncthreads();

    for (int i = tid; i < NC * KPRE; i += 256) {
        unsigned long long k = K[i];
        if (k) {
            float s = __uint_as_float((unsigned)(k >> 32));
            int bin = (int)((s - SCORE_THR) * FSCALE);
            bin = bin < 0 ? 0 : (bin > 1023 ? 1023 : bin);
            atomicAdd(&hist[bin], 1u);
        }
    }
    __syncthreads();

    int lc[4];
    int local = 0;
#pragma unroll
    for (int kk = 0; kk < 4; kk++) { lc[kk] = (int)hist[1023 - (tid * 4 + kk)]; local += lc[kk]; }
    sscan[tid] = local;
    __syncthreads();
    for (int off = 1; off < 256; off <<= 1) {
        int vv = sscan[tid];
        int u = (tid >= off) ? sscan[tid - off] : 0;
        __syncthreads();
        sscan[tid] = vv + u;
        __syncthreads();
    }
    int incl = sscan[tid];
    int excl = incl - local;
    if (excl < MAXB && incl >= MAXB) {
        int run = excl;
#pragma unroll
        for (int kk = 0; kk < 4; kk++) {
            run += lc[kk];
            if (run >= MAXB) { pivot = 1023 - (tid * 4 + kk); break; }
        }
    }
    __syncthreads();
    int P = pivot;

    for (int i = tid; i < NC * KPRE; i += 256) {
        unsigned long long k = K[i];
        if (k) {
            float s = __uint_as_float((unsigned)(k >> 32));
            int bin = (int)((s - SCORE_THR) * FSCALE);
            bin = bin < 0 ? 0 : (bin > 1023 ? 1023 : bin);
            if (bin >= P) {
                unsigned pos = atomicAdd(&cnt, 1u);
                if (pos < SORTF) buf[pos] = k;
            }
        }
    }
    __syncthreads();
    int m = cnt < SORTF ? (int)cnt : SORTF;
    for (int i = tid; i < SORTF; i += 256)
        if (i >= m) buf[i] = 0ULL;
    __syncthreads();

    for (int k2 = 2; k2 <= SORTF; k2 <<= 1) {
        for (int j = k2 >> 1; j > 0; j >>= 1) {
            int ixj = tid ^ j;
            if (ixj > tid) {
                unsigned long long A = buf[tid], Bv = buf[ixj];
                bool desc = ((tid & k2) == 0);
                if (desc ? (A < Bv) : (A > Bv)) { buf[tid] = Bv; buf[ixj] = A; }
            }
            __syncthreads();
        }
    }

    if (tid < MAXB) {
        unsigned long long k = buf[tid];
        float x1 = -1.f, y1 = -1.f, x2 = -1.f, y2 = -1.f, scv = -1.f, lab = -1.f;
        if (k) {
            unsigned bits = (unsigned)(k >> 32);
            scv = __uint_as_float(bits);
            unsigned low = (unsigned)(k & 0xFFFFFFFFu);
            int flatpos = 20479 - (int)(low >> 15);
            int a = (int)(low & 0x7FFFu);
            int cls = flatpos >> 8;
            float4 bb = g_boxes[b * NA + a];
            x1 = bb.x; y1 = bb.y; x2 = bb.z; y2 = bb.w;
            lab = (float)cls;
        }
        float* ob = out;
        float* os = out + NB * MAXB * 4;
        float* ol = out + NB * MAXB * 5;
        ob[(b * MAXB + tid) * 4 + 0] = x1;
        ob[(b * MAXB + tid) * 4 + 1] = y1;
        ob[(b * MAXB + tid) * 4 + 2] = x2;
        ob[(b * MAXB + tid) * 4 + 3] = y2;
        os[b * MAXB + tid] = scv;
        ol[b * MAXB + tid] = lab;
    }
}

// ---------------------------------------------------------------------------
extern "C" void kernel_launch(void* const* d_in, const int* in_sizes, int n_in,
                              void* d_out, int out_size)
{
    const float* p5 = (const float*)d_in[0];
    const float* p4 = (const float*)d_in[1];
    const float* p3 = (const float*)d_in[2];
    float* out = (float*)d_out;

    decode_kernel<<<NB * DECBLK, 256>>>(p5, p4, p3);
    nms_kernel<<<NB * NC, 256>>>(p5, p4, p3);
    final_kernel<<<NB, 256>>>(out);
}

// round 13
// speedup vs baseline: 3.2257x; 1.0233x over previous
#include <cuda_runtime.h>
#include <math.h>
#include <stdint.h>

#define NB 16
#define NA 25200
#define NC 80
#define KPRE 256
#define MAXB 100
#define CAPB 2048
#define SORTF 256
#define SCORE_THR 0.25f
#define IOU_THR 0.1f
#define T0 0.58f

#define DECBLK 99   // ceil(25200/256) blocks per image

// anchors: p5 (20x20) [0,1200), p4 (40x40) [1200,6000), p3 (80x80) [6000,25200)

__device__ float4 g_boxes[NB * NA];
__device__ unsigned long long g_bucket[(size_t)NB * NC * CAPB];
__device__ unsigned int g_bcount[NB * NC];          // zero-init at load; re-zeroed by nms
__device__ float g_fbrow[(size_t)NB * NC * NA];     // fallback scratch only
__device__ unsigned long long g_keys[NB * NC * KPRE];

__constant__ float c_anch[9][2] = {
    {116.f, 90.f}, {156.f, 198.f}, {373.f, 326.f},
    {30.f, 61.f},  {62.f, 45.f},   {59.f, 119.f},
    {10.f, 13.f},  {16.f, 30.f},   {33.f, 23.f}
};

// ---------------------------------------------------------------------------
__device__ __forceinline__ const float* anchor_ptr(
    const float* p5, const float* p4, const float* p3,
    int b, int gi, int& layer, int& g, float& ratio, int& xi, int& yi, int& sub)
{
    const float* fm;
    int base;
    if (gi < 1200)      { layer = 0; base = 0;    g = 20; fm = p5; ratio = 32.f; }
    else if (gi < 6000) { layer = 1; base = 1200; g = 40; fm = p4; ratio = 16.f; }
    else                { layer = 2; base = 6000; g = 80; fm = p3; ratio = 8.f;  }
    int li = gi - base;
    int cell = li / 3;
    sub = li - cell * 3;
    xi = cell % g;
    yi = cell / g;
    return fm + ((size_t)(b * g + yi) * g + xi) * 255 + sub * 85;
}

__device__ __forceinline__ void scatter_key(int b, int c, float sc, int gi)
{
    int bkt = b * NC + c;
    unsigned pos = atomicAdd(&g_bcount[bkt], 1u);
    if (pos < CAPB)
        g_bucket[(size_t)bkt * CAPB + pos] =
            ((unsigned long long)__float_as_uint(sc) << 32)
            | (unsigned)(0xFFFFFFFFu - (unsigned)gi);
}

// ---------------------------------------------------------------------------
// Pass 1: decode boxes + T0 bucket scatter (R11/R12 structure; class pass now
// walks a ballot mask of conf-passing anchors instead of all 32)
// ---------------------------------------------------------------------------
__global__ __launch_bounds__(256) void decode_kernel(
    const float* __restrict__ p5, const float* __restrict__ p4, const float* __restrict__ p3)
{
    int tid = threadIdx.x;
    int b = blockIdx.x / DECBLK;
    int blk = blockIdx.x - b * DECBLK;
    int lane = tid & 31;
    int warp_base = blk * 256 + (tid & ~31);
    int gi = warp_base + lane;

    int wl_first = warp_base < 1200 ? 0 : (warp_base < 6000 ? 1 : 2);
    int wl_lastgi = warp_base + 31;
    int wl_last = wl_lastgi < 1200 ? 0 : (wl_lastgi < 6000 ? 1 : 2);
    bool uniform = (wl_lastgi < NA) && (wl_first == wl_last);

    if (uniform) {
        const float* fm;
        int g, layerbase, arow;
        float ratio;
        if (wl_first == 0)      { fm = p5; g = 20; layerbase = 0;    arow = 0; ratio = 32.f; }
        else if (wl_first == 1) { fm = p4; g = 40; layerbase = 1200; arow = 3; ratio = 16.f; }
        else                    { fm = p3; g = 80; layerbase = 6000; arow = 6; ratio = 8.f;  }

        int li = gi - layerbase;
        int cell = li / 3;
        int sub = li - cell * 3;
        int xi = cell % g;
        int yi = cell / g;
        const float* v = fm + (size_t)b * g * g * 255 + (size_t)li * 85;

        float t0 = v[0], t1 = v[1], t2 = v[2], t3 = v[3], t4 = v[4];
        float sx = 1.f / (1.f + expf(-t0));
        float sy = 1.f / (1.f + expf(-t1));
        float cx = (sx + (float)xi) * ratio;
        float cy = (sy + (float)yi) * ratio;
        float w = expf(t2) * c_anch[arow + sub][0];
        float h = expf(t3) * c_anch[arow + sub][1];
        float conf = 1.f / (1.f + expf(-t4));

        g_boxes[b * NA + gi] = make_float4(cx - w * 0.5f, cy - h * 0.5f, cx + w * 0.5f, cy + h * 0.5f);

        float thr = __int_as_float(0x7F800000);
        if (conf > T0) {
            float q = T0 / conf;
            thr = logf(q / (1.f - q)) - 1e-3f;
        }

        // walk only conf-passing anchors of this warp
        unsigned amask = __ballot_sync(0xFFFFFFFFu, conf > T0);
        const float* vbase = fm + (size_t)b * g * g * 255 + (size_t)(warp_base - layerbase) * 85;
        while (amask) {
            int al = __ffs(amask) - 1;
            amask &= amask - 1;
            float thr_a = __shfl_sync(0xFFFFFFFFu, thr, al);
            float conf_a = __shfl_sync(0xFFFFFFFFu, conf, al);
            const float* va = vbase + al * 85 + 5;
            int gia = warp_base + al;
#pragma unroll
            for (int r = 0; r < 3; r++) {
                int c = lane + r * 32;
                if (c < NC) {
                    float xc = va[c];                  // coalesced across lanes
                    if (xc > thr_a) {
                        float sc = conf_a * (1.f / (1.f + expf(-xc)));
                        if (sc >= T0) scatter_key(b, c, sc, gia);
                    }
                }
            }
        }
    } else {
        if (gi >= NA) return;

        int layer, g, xi, yi, sub;
        float ratio;
        const float* v = anchor_ptr(p5, p4, p3, b, gi, layer, g, ratio, xi, yi, sub);

        float t0 = v[0], t1 = v[1], t2 = v[2], t3 = v[3], t4 = v[4];
        float sx = 1.f / (1.f + expf(-t0));
        float sy = 1.f / (1.f + expf(-t1));
        float cx = (sx + (float)xi) * ratio;
        float cy = (sy + (float)yi) * ratio;
        float w = expf(t2) * c_anch[layer * 3 + sub][0];
        float h = expf(t3) * c_anch[layer * 3 + sub][1];
        float conf = 1.f / (1.f + expf(-t4));

        g_boxes[b * NA + gi] = make_float4(cx - w * 0.5f, cy - h * 0.5f, cx + w * 0.5f, cy + h * 0.5f);

        float thr = __int_as_float(0x7F800000);
        if (conf > T0) {
            float q = T0 / conf;
            thr = logf(q / (1.f - q)) - 1e-3f;
        }

#pragma unroll
        for (int c = 0; c < NC; c++) {
            float xc = v[5 + c];
            if (xc > thr) {
                float sc = conf * (1.f / (1.f + expf(-xc)));
                if (sc >= T0) scatter_key(b, c, sc, gi);
            }
        }
    }
}

// ---------------------------------------------------------------------------
// Pass 2: prune (256-bin hist pivot -> compact) -> bitonic sort -> barrier NMS
// smem-dieted to ~20.5 KB for 8 blocks/SM
// ---------------------------------------------------------------------------
__global__ __launch_bounds__(256) void nms_kernel(
    const float* __restrict__ p5, const float* __restrict__ p4, const float* __restrict__ p3)
{
    __shared__ unsigned long long buf[1536];   // 12 KB: stage [0,1024) + compact [1024,1536)
    __shared__ unsigned int hist[256];         // 1 KB
    __shared__ int sscan[256];                 // fallback scan / warp sums
    __shared__ unsigned int cnt;
    __shared__ int pivot;
    __shared__ int soff, ssn;
    __shared__ float4 bbox[KPRE];              // 4 KB
    __shared__ float barea_s[KPRE];
    __shared__ int supp[KPRE];
    __shared__ unsigned int kwarp[8];

    int bc = blockIdx.x;
    int b = bc / NC;
    int c = bc - b * NC;
    int tid = threadIdx.x;
    int lane = tid & 31;
    int wid = tid >> 5;

    unsigned n_raw = g_bcount[bc];

    if (n_raw >= KPRE && n_raw <= 1024) {
        // ---- fast path: load keys + 256-bin histogram ----
        const unsigned long long* BK = g_bucket + (size_t)bc * CAPB;
        const float BSCALE = 255.0f / (1.0f - T0);
        int n = (int)n_raw;

        if (tid < 256) hist[tid] = 0;
        if (tid == 0) { cnt = 0; pivot = 0; }
        __syncthreads();

        for (int i = tid; i < n; i += 256) {
            unsigned long long k = BK[i];
            buf[i] = k;
            float s = __uint_as_float((unsigned)(k >> 32));
            int bin = (int)((s - T0) * BSCALE);
            bin = bin < 0 ? 0 : (bin > 255 ? 255 : bin);
            atomicAdd(&hist[bin], 1u);
        }
        __syncthreads();

        // pivot for rank KPRE: thread tid owns descending-rank bin 255-tid
        int local = (int)hist[255 - tid];
        int x = local;
#pragma unroll
        for (int d = 1; d < 32; d <<= 1) {
            int y = __shfl_up_sync(0xFFFFFFFFu, x, d);
            if (lane >= d) x += y;
        }
        if (lane == 31) sscan[wid] = x;
        __syncthreads();
        int off = 0;
        for (int w = 0; w < wid; w++) off += sscan[w];
        int incl = x + off;
        int excl = incl - local;
        if (excl < KPRE && incl >= KPRE) pivot = 255 - tid;
        __syncthreads();
        int P = pivot;

        // compact keys with bin >= P into buf[1024..1536)
        for (int i = tid; i < n; i += 256) {
            unsigned long long k = buf[i];
            float s = __uint_as_float((unsigned)(k >> 32));
            int bin = (int)((s - T0) * BSCALE);
            bin = bin < 0 ? 0 : (bin > 255 ? 255 : bin);
            if (bin >= P) {
                unsigned pos = atomicAdd(&cnt, 1u);
                if (pos < 512) buf[1024 + pos] = k;
            }
        }
        __syncthreads();
        int m = (int)cnt;
        if (m <= 512) {
            int sp = (m <= SORTF) ? SORTF : 512;
            if (tid == 0) { soff = 1024; ssn = sp; }
            for (int i = tid; i < sp; i += 256)
                if (i >= m) buf[1024 + i] = 0ULL;
            __syncthreads();
        } else {
            // pivot-bin overflow (practically impossible): sort full staging
            if (tid == 0) { soff = 0; ssn = 1024; }
            for (int i = tid; i < 1024; i += 256)
                if (i >= n) buf[i] = 0ULL;
            __syncthreads();
        }
    } else {
        // ---- exact fallback: recompute row, 256-bin hist-pivot, collect ----
        float* row = g_fbrow + (size_t)bc * NA;
        const float FSCALE = 255.0f / 0.75f;
        if (tid < 256) hist[tid] = 0;
        if (tid == 0) { cnt = 0; pivot = 0; }
        __syncthreads();

        for (int gi = tid; gi < NA; gi += 256) {
            int layer, g, xi, yi, sub;
            float ratio;
            const float* v = anchor_ptr(p5, p4, p3, b, gi, layer, g, ratio, xi, yi, sub);
            float conf = 1.f / (1.f + expf(-v[4]));
            float sc = conf * (1.f / (1.f + expf(-v[5 + c])));
            float s = (sc > SCORE_THR) ? sc : -1.f;
            row[gi] = s;
            if (s > 0.f) {
                int bin = (int)((s - SCORE_THR) * FSCALE);
                bin = bin < 0 ? 0 : (bin > 255 ? 255 : bin);
                atomicAdd(&hist[bin], 1u);
            }
        }
        __syncthreads();

        int local = (int)hist[255 - tid];
        sscan[tid] = local;
        __syncthreads();
        for (int off2 = 1; off2 < 256; off2 <<= 1) {
            int vv = sscan[tid];
            int u = (tid >= off2) ? sscan[tid - off2] : 0;
            __syncthreads();
            sscan[tid] = vv + u;
            __syncthreads();
        }
        int incl = sscan[tid];
        int excl = incl - local;
        if (excl < KPRE && incl >= KPRE) pivot = 255 - tid;
        __syncthreads();
        int P = pivot;

        for (int gi = tid; gi < NA; gi += 256) {
            float s = row[gi];
            if (s > 0.f) {
                int bin = (int)((s - SCORE_THR) * FSCALE);
                bin = bin < 0 ? 0 : (bin > 255 ? 255 : bin);
                if (bin >= P) {
                    unsigned pos = atomicAdd(&cnt, 1u);
                    if (pos < 1024)
                        buf[pos] = ((unsigned long long)__float_as_uint(s) << 32)
                                 | (unsigned)(0xFFFFFFFFu - (unsigned)gi);
                }
            }
        }
        __syncthreads();
        int m = cnt < 1024u ? (int)cnt : 1024;
        if (tid == 0) { soff = 0; ssn = 1024; }
        for (int i = tid; i < 1024; i += 256)
            if (i >= m) buf[i] = 0ULL;
        __syncthreads();
    }

    unsigned long long* sb = buf + soff;
    int sn = ssn;

    // bitonic sort descending
    for (int k = 2; k <= sn; k <<= 1) {
        for (int j = k >> 1; j > 0; j >>= 1) {
            for (int i = tid; i < sn; i += 256) {
                int ixj = i ^ j;
                if (ixj > i) {
                    unsigned long long A = sb[i], Bv = sb[ixj];
                    bool desc = ((i & k) == 0);
                    if (desc ? (A < Bv) : (A > Bv)) { sb[i] = Bv; sb[ixj] = A; }
                }
            }
            __syncthreads();
        }
    }

    // top-256 -> smem box arrays (score/anchor stay in registers)
    unsigned long long key = sb[tid];
    bool valid = key != 0ULL;
    float sc = -1.f;
    int a = 0;
    if (valid) {
        sc = __uint_as_float((unsigned)(key >> 32));
        a = (int)(0xFFFFFFFFu - (unsigned)(key & 0xFFFFFFFFu));
    }
    float4 bb = valid ? g_boxes[b * NA + a] : make_float4(0.f, 0.f, 0.f, 0.f);
    float area = fmaxf(bb.z - bb.x, 0.f) * fmaxf(bb.w - bb.y, 0.f);
    bbox[tid] = bb;
    barea_s[tid] = area;
    supp[tid] = valid ? 0 : 1;
    __syncthreads();

    // greedy NMS barrier loop with early exit at MAXB keeps (R12-proven)
    bool msupp = !valid;
    int kept_cnt = 0;
    for (int i = 0; i < KPRE - 1; i++) {
        int supp_i = supp[i];
        if (!supp_i) {
            kept_cnt++;
            if (kept_cnt >= MAXB) break;
            if (tid > i && !msupp) {
                float4 ob = bbox[i];
                float iw = fminf(bb.z, ob.z) - fmaxf(bb.x, ob.x);
                float ih = fminf(bb.w, ob.w) - fmaxf(bb.y, ob.y);
                iw = fmaxf(iw, 0.f);
                ih = fmaxf(ih, 0.f);
                float inter = iw * ih;
                float uni = area + barea_s[i] - inter;
                float iou = inter / fmaxf(uni, 1e-9f);
                if (iou > IOU_THR) { msupp = true; supp[tid] = 1; }
            }
        }
        __syncthreads();
    }
    __syncthreads();

    // keep + rank via ballot (R12-proven)
    bool keep = !msupp;
    unsigned kb = __ballot_sync(0xFFFFFFFFu, keep);
    if (lane == 0) kwarp[wid] = kb;
    __syncthreads();
    if (keep) {
        int rank = __popc(kb & (0xFFFFFFFFu >> (31 - lane)));
        for (int w = 0; w < wid; w++) rank += __popc(kwarp[w]);
        keep = rank <= MAXB;
    }

    unsigned long long outkey = 0ULL;
    if (keep) {
        int flatpos = c * KPRE + tid;
        unsigned low = ((unsigned)(20479 - flatpos) << 15) | (unsigned)a;
        outkey = ((unsigned long long)__float_as_uint(sc) << 32) | low;
    }
    g_keys[(size_t)b * NC * KPRE + c * KPRE + tid] = outkey;

    if (tid == 0) g_bcount[bc] = 0;   // reset for next graph replay
}

// ---------------------------------------------------------------------------
// Pass 3: per-image top-100 (byte-identical to R10-R12)
// ---------------------------------------------------------------------------
__global__ __launch_bounds__(256) void final_kernel(float* __restrict__ out)
{
    __shared__ unsigned int hist[1024];
    __shared__ unsigned long long buf[SORTF];
    __shared__ int sscan[256];
    __shared__ unsigned int cnt;
    __shared__ int pivot;

    int b = blockIdx.x;
    int tid = threadIdx.x;
    const unsigned long long* K = g_keys + (size_t)b * NC * KPRE;
    const float FSCALE = 1023.0f / 0.75f;

    for (int i = tid; i < 1024; i += 256) hist[i] = 0;
    if (tid == 0) { cnt = 0; pivot = 0; }
    __syncthreads();

    for (int i = tid; i < NC * KPRE; i += 256) {
        unsigned long long k = K[i];
        if (k) {
            float s = __uint_as_float((unsigned)(k >> 32));
            int bin = (int)((s - SCORE_THR) * FSCALE);
            bin = bin < 0 ? 0 : (bin > 1023 ? 1023 : bin);
            atomicAdd(&hist[bin], 1u);
        }
    }
    __syncthreads();

    int lc[4];
    int local = 0;
#pragma unroll
    for (int kk = 0; kk < 4; kk++) { lc[kk] = (int)hist[1023 - (tid * 4 + kk)]; local += lc[kk]; }
    sscan[tid] = local;
    __syncthreads();
    for (int off = 1; off < 256; off <<= 1) {
        int vv = sscan[tid];
        int u = (tid >= off) ? sscan[tid - off] : 0;
        __syncthreads();
        sscan[tid] = vv + u;
        __syncthreads();
    }
    int incl = sscan[tid];
    int excl = incl - local;
    if (excl < MAXB && incl >= MAXB) {
        int run = excl;
#pragma unroll
        for (int kk = 0; kk < 4; kk++) {
            run += lc[kk];
            if (run >= MAXB) { pivot = 1023 - (tid * 4 + kk); break; }
        }
    }
    __syncthreads();
    int P = pivot;

    for (int i = tid; i < NC * KPRE; i += 256) {
        unsigned long long k = K[i];
        if (k) {
            float s = __uint_as_float((unsigned)(k >> 32));
            int bin = (int)((s - SCORE_THR) * FSCALE);
            bin = bin < 0 ? 0 : (bin > 1023 ? 1023 : bin);
            if (bin >= P) {
                unsigned pos = atomicAdd(&cnt, 1u);
                if (pos < SORTF) buf[pos] = k;
            }
        }
    }
    __syncthreads();
    int m = cnt < SORTF ? (int)cnt : SORTF;
    for (int i = tid; i < SORTF; i += 256)
        if (i >= m) buf[i] = 0ULL;
    __syncthreads();

    for (int k2 = 2; k2 <= SORTF; k2 <<= 1) {
        for (int j = k2 >> 1; j > 0; j >>= 1) {
            int ixj = tid ^ j;
            if (ixj > tid) {
                unsigned long long A = buf[tid], Bv = buf[ixj];
                bool desc = ((tid & k2) == 0);
                if (desc ? (A < Bv) : (A > Bv)) { buf[tid] = Bv; buf[ixj] = A; }
            }
            __syncthreads();
        }
    }

    if (tid < MAXB) {
        unsigned long long k = buf[tid];
        float x1 = -1.f, y1 = -1.f, x2 = -1.f, y2 = -1.f, scv = -1.f, lab = -1.f;
        if (k) {
            unsigned bits = (unsigned)(k >> 32);
            scv = __uint_as_float(bits);
            unsigned low = (unsigned)(k & 0xFFFFFFFFu);
            int flatpos = 20479 - (int)(low >> 15);
            int a = (int)(low & 0x7FFFu);
            int cls = flatpos >> 8;
            float4 bb = g_boxes[b * NA + a];
            x1 = bb.x; y1 = bb.y; x2 = bb.z; y2 = bb.w;
            lab = (float)cls;
        }
        float* ob = out;
        float* os = out + NB * MAXB * 4;
        float* ol = out + NB * MAXB * 5;
        ob[(b * MAXB + tid) * 4 + 0] = x1;
        ob[(b * MAXB + tid) * 4 + 1] = y1;
        ob[(b * MAXB + tid) * 4 + 2] = x2;
        ob[(b * MAXB + tid) * 4 + 3] = y2;
        os[b * MAXB + tid] = scv;
        ol[b * MAXB + tid] = lab;
    }
}

// ---------------------------------------------------------------------------
extern "C" void kernel_launch(void* const* d_in, const int* in_sizes, int n_in,
                              void* d_out, int out_size)
{
    const float* p5 = (const float*)d_in[0];
    const float* p4 = (const float*)d_in[1];
    const float* p3 = (const float*)d_in[2];
    float* out = (float*)d_out;

    decode_kernel<<<NB * DECBLK, 256>>>(p5, p4, p3);
    nms_kernel<<<NB * NC, 256>>>(p5, p4, p3);
    final_kernel<<<NB, 256>>>(out);
}

// round 14
// speedup vs baseline: 3.2970x; 1.0221x over previous
#include <cuda_runtime.h>
#include <math.h>
#include <stdint.h>

#define NB 16
#define NA 25200
#define NC 80
#define KPRE 256
#define MAXB 100
#define CAPB 2048
#define SORTF 256
#define SCORE_THR 0.25f
#define IOU_THR 0.1f
#define T0 0.58f

#define DECBLK 99            // ceil(25200/256) block-units per image
#define NUNITS_DEC (NB * DECBLK)
#define NUNITS_NMS (NB * NC)
#define GRID_WAVE 1184       // 148 SMs x 8 blocks: one full resident wave

// anchors: p5 (20x20) [0,1200), p4 (40x40) [1200,6000), p3 (80x80) [6000,25200)

__device__ float4 g_boxes[NB * NA];
__device__ unsigned long long g_bucket[(size_t)NB * NC * CAPB];
__device__ unsigned int g_bcount[NB * NC];          // zero-init at load; re-zeroed by nms
__device__ float g_fbrow[(size_t)NB * NC * NA];     // fallback scratch only
__device__ unsigned long long g_keys[NB * NC * KPRE];

__constant__ float c_anch[9][2] = {
    {116.f, 90.f}, {156.f, 198.f}, {373.f, 326.f},
    {30.f, 61.f},  {62.f, 45.f},   {59.f, 119.f},
    {10.f, 13.f},  {16.f, 30.f},   {33.f, 23.f}
};

// ---------------------------------------------------------------------------
__device__ __forceinline__ const float* anchor_ptr(
    const float* p5, const float* p4, const float* p3,
    int b, int gi, int& layer, int& g, float& ratio, int& xi, int& yi, int& sub)
{
    const float* fm;
    int base;
    if (gi < 1200)      { layer = 0; base = 0;    g = 20; fm = p5; ratio = 32.f; }
    else if (gi < 6000) { layer = 1; base = 1200; g = 40; fm = p4; ratio = 16.f; }
    else                { layer = 2; base = 6000; g = 80; fm = p3; ratio = 8.f;  }
    int li = gi - base;
    int cell = li / 3;
    sub = li - cell * 3;
    xi = cell % g;
    yi = cell / g;
    return fm + ((size_t)(b * g + yi) * g + xi) * 255 + sub * 85;
}

__device__ __forceinline__ void scatter_key(int b, int c, float sc, int gi)
{
    int bkt = b * NC + c;
    unsigned pos = atomicAdd(&g_bcount[bkt], 1u);
    if (pos < CAPB)
        g_bucket[(size_t)bkt * CAPB + pos] =
            ((unsigned long long)__float_as_uint(sc) << 32)
            | (unsigned)(0xFFFFFFFFu - (unsigned)gi);
}

// ---------------------------------------------------------------------------
// decode unit body (identical math/structure to passing R13)
// ---------------------------------------------------------------------------
__device__ __forceinline__ void decode_unit(
    int unit, const float* __restrict__ p5, const float* __restrict__ p4,
    const float* __restrict__ p3)
{
    int tid = threadIdx.x;
    int b = unit / DECBLK;
    int blk = unit - b * DECBLK;
    int lane = tid & 31;
    int warp_base = blk * 256 + (tid & ~31);
    int gi = warp_base + lane;

    int wl_first = warp_base < 1200 ? 0 : (warp_base < 6000 ? 1 : 2);
    int wl_lastgi = warp_base + 31;
    int wl_last = wl_lastgi < 1200 ? 0 : (wl_lastgi < 6000 ? 1 : 2);
    bool uniform = (wl_lastgi < NA) && (wl_first == wl_last);

    if (uniform) {
        const float* fm;
        int g, layerbase, arow;
        float ratio;
        if (wl_first == 0)      { fm = p5; g = 20; layerbase = 0;    arow = 0; ratio = 32.f; }
        else if (wl_first == 1) { fm = p4; g = 40; layerbase = 1200; arow = 3; ratio = 16.f; }
        else                    { fm = p3; g = 80; layerbase = 6000; arow = 6; ratio = 8.f;  }

        int li = gi - layerbase;
        int cell = li / 3;
        int sub = li - cell * 3;
        int xi = cell % g;
        int yi = cell / g;
        const float* v = fm + (size_t)b * g * g * 255 + (size_t)li * 85;

        float t0 = v[0], t1 = v[1], t2 = v[2], t3 = v[3], t4 = v[4];
        float sx = 1.f / (1.f + expf(-t0));
        float sy = 1.f / (1.f + expf(-t1));
        float cx = (sx + (float)xi) * ratio;
        float cy = (sy + (float)yi) * ratio;
        float w = expf(t2) * c_anch[arow + sub][0];
        float h = expf(t3) * c_anch[arow + sub][1];
        float conf = 1.f / (1.f + expf(-t4));

        g_boxes[b * NA + gi] = make_float4(cx - w * 0.5f, cy - h * 0.5f, cx + w * 0.5f, cy + h * 0.5f);

        float thr = __int_as_float(0x7F800000);
        if (conf > T0) {
            float q = T0 / conf;
            thr = logf(q / (1.f - q)) - 1e-3f;
        }

        unsigned amask = __ballot_sync(0xFFFFFFFFu, conf > T0);
        const float* vbase = fm + (size_t)b * g * g * 255 + (size_t)(warp_base - layerbase) * 85;
        while (amask) {
            int al = __ffs(amask) - 1;
            amask &= amask - 1;
            float thr_a = __shfl_sync(0xFFFFFFFFu, thr, al);
            float conf_a = __shfl_sync(0xFFFFFFFFu, conf, al);
            const float* va = vbase + al * 85 + 5;
            int gia = warp_base + al;
#pragma unroll
            for (int r = 0; r < 3; r++) {
                int c = lane + r * 32;
                if (c < NC) {
                    float xc = va[c];
                    if (xc > thr_a) {
                        float sc = conf_a * (1.f / (1.f + expf(-xc)));
                        if (sc >= T0) scatter_key(b, c, sc, gia);
                    }
                }
            }
        }
    } else if (gi < NA) {
        int layer, g, xi, yi, sub;
        float ratio;
        const float* v = anchor_ptr(p5, p4, p3, b, gi, layer, g, ratio, xi, yi, sub);

        float t0 = v[0], t1 = v[1], t2 = v[2], t3 = v[3], t4 = v[4];
        float sx = 1.f / (1.f + expf(-t0));
        float sy = 1.f / (1.f + expf(-t1));
        float cx = (sx + (float)xi) * ratio;
        float cy = (sy + (float)yi) * ratio;
        float w = expf(t2) * c_anch[layer * 3 + sub][0];
        float h = expf(t3) * c_anch[layer * 3 + sub][1];
        float conf = 1.f / (1.f + expf(-t4));

        g_boxes[b * NA + gi] = make_float4(cx - w * 0.5f, cy - h * 0.5f, cx + w * 0.5f, cy + h * 0.5f);

        float thr = __int_as_float(0x7F800000);
        if (conf > T0) {
            float q = T0 / conf;
            thr = logf(q / (1.f - q)) - 1e-3f;
        }

#pragma unroll
        for (int c = 0; c < NC; c++) {
            float xc = v[5 + c];
            if (xc > thr) {
                float sc = conf * (1.f / (1.f + expf(-xc)));
                if (sc >= T0) scatter_key(b, c, sc, gi);
            }
        }
    }
}

// ---------------------------------------------------------------------------
// Pass 1: grid-stride over decode units (one full resident wave)
// ---------------------------------------------------------------------------
__global__ __launch_bounds__(256) void decode_kernel(
    const float* __restrict__ p5, const float* __restrict__ p4, const float* __restrict__ p3)
{
    for (int u = blockIdx.x; u < NUNITS_DEC; u += gridDim.x)
        decode_unit(u, p5, p4, p3);
}

// ---------------------------------------------------------------------------
// Pass 2: grid-stride over (image,class) units; unit body identical to R13
// ---------------------------------------------------------------------------
__global__ __launch_bounds__(256) void nms_kernel(
    const float* __restrict__ p5, const float* __restrict__ p4, const float* __restrict__ p3)
{
    __shared__ unsigned long long buf[1536];   // 12 KB: stage [0,1024) + compact [1024,1536)
    __shared__ unsigned int hist[256];         // 1 KB
    __shared__ int sscan[256];
    __shared__ unsigned int cnt;
    __shared__ int pivot;
    __shared__ int soff, ssn;
    __shared__ float4 bbox[KPRE];
    __shared__ float barea_s[KPRE];
    __shared__ int supp[KPRE];
    __shared__ unsigned int kwarp[8];

    int tid = threadIdx.x;
    int lane = tid & 31;
    int wid = tid >> 5;

    for (int bc = blockIdx.x; bc < NUNITS_NMS; bc += gridDim.x) {
        int b = bc / NC;
        int c = bc - b * NC;

        unsigned n_raw = g_bcount[bc];

        if (n_raw >= KPRE && n_raw <= 1024) {
            // ---- fast path: load keys + 256-bin histogram ----
            const unsigned long long* BK = g_bucket + (size_t)bc * CAPB;
            const float BSCALE = 255.0f / (1.0f - T0);
            int n = (int)n_raw;

            if (tid < 256) hist[tid] = 0;
            if (tid == 0) { cnt = 0; pivot = 0; }
            __syncthreads();

            for (int i = tid; i < n; i += 256) {
                unsigned long long k = BK[i];
                buf[i] = k;
                float s = __uint_as_float((unsigned)(k >> 32));
                int bin = (int)((s - T0) * BSCALE);
                bin = bin < 0 ? 0 : (bin > 255 ? 255 : bin);
                atomicAdd(&hist[bin], 1u);
            }
            __syncthreads();

            // pivot for rank KPRE via shfl scan
            int local = (int)hist[255 - tid];
            int x = local;
#pragma unroll
            for (int d = 1; d < 32; d <<= 1) {
                int y = __shfl_up_sync(0xFFFFFFFFu, x, d);
                if (lane >= d) x += y;
            }
            if (lane == 31) sscan[wid] = x;
            __syncthreads();
            int off = 0;
            for (int w = 0; w < wid; w++) off += sscan[w];
            int incl = x + off;
            int excl = incl - local;
            if (excl < KPRE && incl >= KPRE) pivot = 255 - tid;
            __syncthreads();
            int P = pivot;

            // compact keys with bin >= P into buf[1024..1536)
            for (int i = tid; i < n; i += 256) {
                unsigned long long k = buf[i];
                float s = __uint_as_float((unsigned)(k >> 32));
                int bin = (int)((s - T0) * BSCALE);
                bin = bin < 0 ? 0 : (bin > 255 ? 255 : bin);
                if (bin >= P) {
                    unsigned pos = atomicAdd(&cnt, 1u);
                    if (pos < 512) buf[1024 + pos] = k;
                }
            }
            __syncthreads();
            int m = (int)cnt;
            if (m <= 512) {
                int sp = (m <= SORTF) ? SORTF : 512;
                if (tid == 0) { soff = 1024; ssn = sp; }
                for (int i = tid; i < sp; i += 256)
                    if (i >= m) buf[1024 + i] = 0ULL;
                __syncthreads();
            } else {
                if (tid == 0) { soff = 0; ssn = 1024; }
                for (int i = tid; i < 1024; i += 256)
                    if (i >= n) buf[i] = 0ULL;
                __syncthreads();
            }
        } else {
            // ---- exact fallback: recompute row, 256-bin hist-pivot, collect ----
            float* row = g_fbrow + (size_t)bc * NA;
            const float FSCALE = 255.0f / 0.75f;
            if (tid < 256) hist[tid] = 0;
            if (tid == 0) { cnt = 0; pivot = 0; }
            __syncthreads();

            for (int gi = tid; gi < NA; gi += 256) {
                int layer, g, xi, yi, sub;
                float ratio;
                const float* v = anchor_ptr(p5, p4, p3, b, gi, layer, g, ratio, xi, yi, sub);
                float conf = 1.f / (1.f + expf(-v[4]));
                float sc = conf * (1.f / (1.f + expf(-v[5 + c])));
                float s = (sc > SCORE_THR) ? sc : -1.f;
                row[gi] = s;
                if (s > 0.f) {
                    int bin = (int)((s - SCORE_THR) * FSCALE);
                    bin = bin < 0 ? 0 : (bin > 255 ? 255 : bin);
                    atomicAdd(&hist[bin], 1u);
                }
            }
            __syncthreads();

            int local = (int)hist[255 - tid];
            sscan[tid] = local;
            __syncthreads();
            for (int off2 = 1; off2 < 256; off2 <<= 1) {
                int vv = sscan[tid];
                int u = (tid >= off2) ? sscan[tid - off2] : 0;
                __syncthreads();
                sscan[tid] = vv + u;
                __syncthreads();
            }
            int incl = sscan[tid];
            int excl = incl - local;
            if (excl < KPRE && incl >= KPRE) pivot = 255 - tid;
            __syncthreads();
            int P = pivot;

            for (int gi = tid; gi < NA; gi += 256) {
                float s = row[gi];
                if (s > 0.f) {
                    int bin = (int)((s - SCORE_THR) * FSCALE);
                    bin = bin < 0 ? 0 : (bin > 255 ? 255 : bin);
                    if (bin >= P) {
                        unsigned pos = atomicAdd(&cnt, 1u);
                        if (pos < 1024)
                            buf[pos] = ((unsigned long long)__float_as_uint(s) << 32)
                                     | (unsigned)(0xFFFFFFFFu - (unsigned)gi);
                    }
                }
            }
            __syncthreads();
            int m = cnt < 1024u ? (int)cnt : 1024;
            if (tid == 0) { soff = 0; ssn = 1024; }
            for (int i = tid; i < 1024; i += 256)
                if (i >= m) buf[i] = 0ULL;
            __syncthreads();
        }

        unsigned long long* sb = buf + soff;
        int sn = ssn;

        // bitonic sort descending
        for (int k = 2; k <= sn; k <<= 1) {
            for (int j = k >> 1; j > 0; j >>= 1) {
                for (int i = tid; i < sn; i += 256) {
                    int ixj = i ^ j;
                    if (ixj > i) {
                        unsigned long long A = sb[i], Bv = sb[ixj];
                        bool desc = ((i & k) == 0);
                        if (desc ? (A < Bv) : (A > Bv)) { sb[i] = Bv; sb[ixj] = A; }
                    }
                }
                __syncthreads();
            }
        }

        // top-256 -> smem box arrays
        unsigned long long key = sb[tid];
        bool valid = key != 0ULL;
        float sc = -1.f;
        int a = 0;
        if (valid) {
            sc = __uint_as_float((unsigned)(key >> 32));
            a = (int)(0xFFFFFFFFu - (unsigned)(key & 0xFFFFFFFFu));
        }
        float4 bb = valid ? g_boxes[b * NA + a] : make_float4(0.f, 0.f, 0.f, 0.f);
        float area = fmaxf(bb.z - bb.x, 0.f) * fmaxf(bb.w - bb.y, 0.f);
        bbox[tid] = bb;
        barea_s[tid] = area;
        supp[tid] = valid ? 0 : 1;
        __syncthreads();

        // greedy NMS barrier loop with early exit at MAXB keeps
        bool msupp = !valid;
        int kept_cnt = 0;
        for (int i = 0; i < KPRE - 1; i++) {
            int supp_i = supp[i];
            if (!supp_i) {
                kept_cnt++;
                if (kept_cnt >= MAXB) break;
                if (tid > i && !msupp) {
                    float4 ob = bbox[i];
                    float iw = fminf(bb.z, ob.z) - fmaxf(bb.x, ob.x);
                    float ih = fminf(bb.w, ob.w) - fmaxf(bb.y, ob.y);
                    iw = fmaxf(iw, 0.f);
                    ih = fmaxf(ih, 0.f);
                    float inter = iw * ih;
                    float uni = area + barea_s[i] - inter;
                    float iou = inter / fmaxf(uni, 1e-9f);
                    if (iou > IOU_THR) { msupp = true; supp[tid] = 1; }
                }
            }
            __syncthreads();
        }
        __syncthreads();

        // keep + rank via ballot
        bool keep = !msupp;
        unsigned kb = __ballot_sync(0xFFFFFFFFu, keep);
        if (lane == 0) kwarp[wid] = kb;
        __syncthreads();
        if (keep) {
            int rank = __popc(kb & (0xFFFFFFFFu >> (31 - lane)));
            for (int w = 0; w < wid; w++) rank += __popc(kwarp[w]);
            keep = rank <= MAXB;
        }

        unsigned long long outkey = 0ULL;
        if (keep) {
            int flatpos = c * KPRE + tid;
            unsigned low = ((unsigned)(20479 - flatpos) << 15) | (unsigned)a;
            outkey = ((unsigned long long)__float_as_uint(sc) << 32) | low;
        }
        g_keys[(size_t)b * NC * KPRE + c * KPRE + tid] = outkey;

        if (tid == 0) g_bcount[bc] = 0;   // reset for next graph replay
        __syncthreads();                  // protect shared reuse across units
    }
}

// ---------------------------------------------------------------------------
// Pass 3: per-image top-100 (byte-identical to R10-R13)
// ---------------------------------------------------------------------------
__global__ __launch_bounds__(256) void final_kernel(float* __restrict__ out)
{
    __shared__ unsigned int hist[1024];
    __shared__ unsigned long long buf[SORTF];
    __shared__ int sscan[256];
    __shared__ unsigned int cnt;
    __shared__ int pivot;

    int b = blockIdx.x;
    int tid = threadIdx.x;
    const unsigned long long* K = g_keys + (size_t)b * NC * KPRE;
    const float FSCALE = 1023.0f / 0.75f;

    for (int i = tid; i < 1024; i += 256) hist[i] = 0;
    if (tid == 0) { cnt = 0; pivot = 0; }
    __syncthreads();

    for (int i = tid; i < NC * KPRE; i += 256) {
        unsigned long long k = K[i];
        if (k) {
            float s = __uint_as_float((unsigned)(k >> 32));
            int bin = (int)((s - SCORE_THR) * FSCALE);
            bin = bin < 0 ? 0 : (bin > 1023 ? 1023 : bin);
            atomicAdd(&hist[bin], 1u);
        }
    }
    __syncthreads();

    int lc[4];
    int local = 0;
#pragma unroll
    for (int kk = 0; kk < 4; kk++) { lc[kk] = (int)hist[1023 - (tid * 4 + kk)]; local += lc[kk]; }
    sscan[tid] = local;
    __syncthreads();
    for (int off = 1; off < 256; off <<= 1) {
        int vv = sscan[tid];
        int u = (tid >= off) ? sscan[tid - off] : 0;
        __syncthreads();
        sscan[tid] = vv + u;
        __syncthreads();
    }
    int incl = sscan[tid];
    int excl = incl - local;
    if (excl < MAXB && incl >= MAXB) {
        int run = excl;
#pragma unroll
        for (int kk = 0; kk < 4; kk++) {
            run += lc[kk];
            if (run >= MAXB) { pivot = 1023 - (tid * 4 + kk); break; }
        }
    }
    __syncthreads();
    int P = pivot;

    for (int i = tid; i < NC * KPRE; i += 256) {
        unsigned long long k = K[i];
        if (k) {
            float s = __uint_as_float((unsigned)(k >> 32));
            int bin = (int)((s - SCORE_THR) * FSCALE);
            bin = bin < 0 ? 0 : (bin > 1023 ? 1023 : bin);
            if (bin >= P) {
                unsigned pos = atomicAdd(&cnt, 1u);
                if (pos < SORTF) buf[pos] = k;
            }
        }
    }
    __syncthreads();
    int m = cnt < SORTF ? (int)cnt : SORTF;
    for (int i = tid; i < SORTF; i += 256)
        if (i >= m) buf[i] = 0ULL;
    __syncthreads();

    for (int k2 = 2; k2 <= SORTF; k2 <<= 1) {
        for (int j = k2 >> 1; j > 0; j >>= 1) {
            int ixj = tid ^ j;
            if (ixj > tid) {
                unsigned long long A = buf[tid], Bv = buf[ixj];
                bool desc = ((tid & k2) == 0);
                if (desc ? (A < Bv) : (A > Bv)) { buf[tid] = Bv; buf[ixj] = A; }
            }
            __syncthreads();
        }
    }

    if (tid < MAXB) {
        unsigned long long k = buf[tid];
        float x1 = -1.f, y1 = -1.f, x2 = -1.f, y2 = -1.f, scv = -1.f, lab = -1.f;
        if (k) {
            unsigned bits = (unsigned)(k >> 32);
            scv = __uint_as_float(bits);
            unsigned low = (unsigned)(k & 0xFFFFFFFFu);
            int flatpos = 20479 - (int)(low >> 15);
            int a = (int)(low & 0x7FFFu);
            int cls = flatpos >> 8;
            float4 bb = g_boxes[b * NA + a];
            x1 = bb.x; y1 = bb.y; x2 = bb.z; y2 = bb.w;
            lab = (float)cls;
        }
        float* ob = out;
        float* os = out + NB * MAXB * 4;
        float* ol = out + NB * MAXB * 5;
        ob[(b * MAXB + tid) * 4 + 0] = x1;
        ob[(b * MAXB + tid) * 4 + 1] = y1;
        ob[(b * MAXB + tid) * 4 + 2] = x2;
        ob[(b * MAXB + tid) * 4 + 3] = y2;
        os[b * MAXB + tid] = scv;
        ol[b * MAXB + tid] = lab;
    }
}

// ---------------------------------------------------------------------------
extern "C" void kernel_launch(void* const* d_in, const int* in_sizes, int n_in,
                              void* d_out, int out_size)
{
    const float* p5 = (const float*)d_in[0];
    const float* p4 = (const float*)d_in[1];
    const float* p3 = (const float*)d_in[2];
    float* out = (float*)d_out;

    int gdec = GRID_WAVE < NUNITS_DEC ? GRID_WAVE : NUNITS_DEC;
    int gnms = GRID_WAVE < NUNITS_NMS ? GRID_WAVE : NUNITS_NMS;

    decode_kernel<<<gdec, 256>>>(p5, p4, p3);
    nms_kernel<<<gnms, 256>>>(p5, p4, p3);
    final_kernel<<<NB, 256>>>(out);
}